// round 1
// baseline (speedup 1.0000x reference)
#include <cuda_runtime.h>
#include <math.h>

#define NM 100000
#define ND 20000
#define NA 50000
#define E0 300000
#define ETOT 600000
#define NB 98   // ceil(NM/1024)

// ---------------- scratch (static device memory; no allocs) ----------------
__device__ float d_q0[NM * 128];
__device__ float d_s0[NM * 8];
__device__ float d_ktdm[ND * 128];
__device__ float d_mtdm[ND * 128];
__device__ float d_ktam[NA * 128];
__device__ float d_mtam[NA * 128];
__device__ int   d_counts[NM];
__device__ int   d_cursor[NM];
__device__ int   d_rowptr[NM + 1];
__device__ int   d_bsum[128];
__device__ int   d_eidx[ETOT];

__device__ float d_WeffK0[128 * 128], d_WeffV0[128 * 128];
__device__ float d_WeffK1[128 * 128], d_WeffV1[128 * 128];
__device__ float d_beffK0[128], d_beffV0[128], d_beffK1[128], d_beffV1[128];
__device__ float d_WK0[128 * 128], d_WV0[128 * 128], d_WK1[128 * 128], d_WV1[128 * 128];
__device__ float d_bK0[128], d_bV0[128], d_bK1[128], d_bV1[128];
__device__ float d_Wqf[256 * 128];
__device__ float d_bqf[128];
__device__ float d_Wsf[256 * 8];
__device__ float d_bsf[8];
__device__ float d_Wcomb[128 * 8];
__device__ float d_tmp8[8];
__device__ float d_cvec[8];
__device__ float d_gs[1];

// ---------------- tiny weight-composition kernels ----------------

// Weff[i][h*16+f] = sum_d Win[i][h*16+d] * A[h][d][f]   (block-diag compose)
// blockIdx.x in [0,129): row 128 composes the bias vector.
__global__ void bd_compose(const float* __restrict__ Win, const float* __restrict__ bin,
                           const float* __restrict__ A,
                           float* __restrict__ Weff, float* __restrict__ beff) {
    int col = threadIdx.x;              // 0..127
    int i = blockIdx.x;                 // 0..128
    int h = col >> 4, f = col & 15;
    const float* arow = A + h * 256 + f;  // A[h][d][f], stride 16 over d
    const float* w = (i < 128) ? (Win + i * 128 + h * 16) : (bin + h * 16);
    float s = 0.f;
#pragma unroll
    for (int d = 0; d < 16; d++) s += w[d] * arow[d * 16];
    if (i < 128) Weff[i * 128 + col] = s;
    else         beff[col] = s;
}

// C[M x N] = A[M x K] @ B[K x N] (+ add[n] if add != nullptr). Tiny sizes only.
__global__ void smallmm(const float* __restrict__ A, const float* __restrict__ B,
                        const float* __restrict__ add, float* __restrict__ C,
                        int M, int K, int N) {
    int t = blockIdx.x * blockDim.x + threadIdx.x;
    if (t >= M * N) return;
    int m = t / N, n = t - m * N;
    float s = add ? add[n] : 0.f;
    for (int k = 0; k < K; k++) s += A[m * K + k] * B[k * N + n];
    C[t] = s;
}

__global__ void make_consts(const float* __restrict__ skip, const float* __restrict__ blin) {
    int t = threadIdx.x;
    float gg = 1.f / (1.f + expf(-skip[0]));
    if (t == 0) d_gs[0] = gg;
    if (t < 8) d_cvec[t] = gg * d_tmp8[t] + blin[t];
}

// ---------------- main fp32 GEMM: C[M x 128] = A[M x K] @ W[K x 128] + bias ----------------
// Tile 128x128, BK=16, 256 threads, 8x8 micro-tile per thread.
__global__ __launch_bounds__(256, 2)
void gemm_f32(const float* __restrict__ A, const float* __restrict__ W,
              const float* __restrict__ bias, float* __restrict__ C,
              int M, int K) {
    __shared__ float As[16][132];   // padded (row stride 528B, 16B aligned)
    __shared__ float Bs[16][128];

    int tid = threadIdx.x;
    int row0 = blockIdx.x * 128;
    int tx = tid & 15, ty = tid >> 4;

    float acc[8][8];
#pragma unroll
    for (int i = 0; i < 8; i++)
#pragma unroll
        for (int j = 0; j < 8; j++) acc[i][j] = 0.f;

    for (int k0 = 0; k0 < K; k0 += 16) {
        // A tile (transposed store): 128 rows x 16 cols
#pragma unroll
        for (int l = 0; l < 2; l++) {
            int idx = tid + l * 256;          // float4 index 0..511
            int m = idx >> 2;
            int kk = (idx & 3) * 4;
            int gr = row0 + m;
            float4 v = make_float4(0.f, 0.f, 0.f, 0.f);
            if (gr < M) v = *(const float4*)&A[(size_t)gr * K + k0 + kk];
            As[kk + 0][m] = v.x; As[kk + 1][m] = v.y;
            As[kk + 2][m] = v.z; As[kk + 3][m] = v.w;
        }
        // W tile: 16 rows x 128 cols, direct
#pragma unroll
        for (int l = 0; l < 2; l++) {
            int idx = tid + l * 256;
            int kk = idx >> 5;
            int n4 = (idx & 31) * 4;
            *(float4*)&Bs[kk][n4] = *(const float4*)&W[(size_t)(k0 + kk) * 128 + n4];
        }
        __syncthreads();

#pragma unroll 4
        for (int kk = 0; kk < 16; kk++) {
            const float4* ap = (const float4*)&As[kk][ty * 8];
            const float4* bp = (const float4*)&Bs[kk][tx * 8];
            float4 a0 = ap[0], a1 = ap[1];
            float4 b0 = bp[0], b1 = bp[1];
            float a[8] = {a0.x, a0.y, a0.z, a0.w, a1.x, a1.y, a1.z, a1.w};
            float b[8] = {b0.x, b0.y, b0.z, b0.w, b1.x, b1.y, b1.z, b1.w};
#pragma unroll
            for (int i = 0; i < 8; i++)
#pragma unroll
                for (int j = 0; j < 8; j++) acc[i][j] += a[i] * b[j];
        }
        __syncthreads();
    }

#pragma unroll
    for (int i = 0; i < 8; i++) {
        int gr = row0 + ty * 8 + i;
        if (gr < M) {
#pragma unroll
            for (int j = 0; j < 8; j += 4) {
                int c = tx * 8 + j;
                float4 o;
                o.x = acc[i][j + 0] + bias[c + 0];
                o.y = acc[i][j + 1] + bias[c + 1];
                o.z = acc[i][j + 2] + bias[c + 2];
                o.w = acc[i][j + 3] + bias[c + 3];
                *(float4*)&C[(size_t)gr * 128 + c] = o;
            }
        }
    }
}

// ---------------- thin GEMM for skip path: s0[M x 8] = A[M x 256] @ W[256 x 8] + bias ----------------
__global__ void kernel_s0(const float* __restrict__ A, const float* __restrict__ W,
                          const float* __restrict__ bias, float* __restrict__ C, int M) {
    __shared__ float sW[2048];
    for (int i = threadIdx.x; i < 2048; i += 256) sW[i] = W[i];
    __syncthreads();
    int gw = (blockIdx.x * 256 + threadIdx.x) >> 5;
    int lane = threadIdx.x & 31;
    if (gw >= M) return;
    const float4* a = (const float4*)(A + (size_t)gw * 256);
    float4 v0 = a[lane];
    float4 v1 = a[lane + 32];
    float av[8] = {v0.x, v0.y, v0.z, v0.w, v1.x, v1.y, v1.z, v1.w};
    float o[8] = {0, 0, 0, 0, 0, 0, 0, 0};
    int k0 = lane * 4;
#pragma unroll
    for (int j = 0; j < 8; j++) {
        int k = (j < 4) ? (k0 + j) : (128 + k0 + j - 4);
        const float* wr = &sW[k * 8];
#pragma unroll
        for (int c = 0; c < 8; c++) o[c] += av[j] * wr[c];
    }
#pragma unroll
    for (int off = 16; off > 0; off >>= 1)
#pragma unroll
        for (int c = 0; c < 8; c++) o[c] += __shfl_xor_sync(0xffffffffu, o[c], off);
    if (lane == 0) {
#pragma unroll
        for (int c = 0; c < 8; c++) C[(size_t)gw * 8 + c] = o[c] + bias[c];
    }
}

// ---------------- CSR build (counting sort by destination movie node) ----------------
__global__ void zero_counts() {
    int i = blockIdx.x * blockDim.x + threadIdx.x;
    if (i < NM) d_counts[i] = 0;
}
__global__ void count_edges(const int* __restrict__ dst_dm, const int* __restrict__ dst_am) {
    int e = blockIdx.x * blockDim.x + threadIdx.x;
    if (e < E0) atomicAdd(&d_counts[dst_dm[e]], 1);
    else if (e < ETOT) atomicAdd(&d_counts[dst_am[e - E0]], 1);
}
__global__ void scan_block() {   // 1024 threads/block, NB blocks
    __shared__ int sh[1024];
    int i = blockIdx.x * 1024 + threadIdx.x;
    int v = (i < NM) ? d_counts[i] : 0;
    sh[threadIdx.x] = v;
    __syncthreads();
    for (int off = 1; off < 1024; off <<= 1) {
        int t = (threadIdx.x >= off) ? sh[threadIdx.x - off] : 0;
        __syncthreads();
        sh[threadIdx.x] += t;
        __syncthreads();
    }
    if (i < NM) d_rowptr[i] = sh[threadIdx.x] - v;   // exclusive
    if (threadIdx.x == 1023) d_bsum[blockIdx.x] = sh[1023];
}
__global__ void scan_bsum() {
    if (threadIdx.x == 0) {
        int s = 0;
        for (int b = 0; b < NB; b++) { int v = d_bsum[b]; d_bsum[b] = s; s += v; }
    }
}
__global__ void add_offsets() {
    int i = blockIdx.x * blockDim.x + threadIdx.x;
    if (i < NM) {
        int v = d_rowptr[i] + d_bsum[i >> 10];
        d_rowptr[i] = v;
        d_cursor[i] = v;
    }
    if (i == 0) d_rowptr[NM] = ETOT;
}
__global__ void fill_edges(const int* __restrict__ dst_dm, const int* __restrict__ dst_am) {
    int e = blockIdx.x * blockDim.x + threadIdx.x;
    int d;
    if (e < E0) d = dst_dm[e];
    else if (e < ETOT) d = dst_am[e - E0];
    else return;
    int pos = atomicAdd(&d_cursor[d], 1);
    d_eidx[pos] = e;   // global edge id: [0,E0)=rel0(dm), [E0,2E0)=rel1(am)
}

// ---------------- fused: per-edge attention + softmax-agg + gelu + output head ----------------
__device__ __forceinline__ float gelu_exact(float x) { return x * normcdff(x); }

__global__ __launch_bounds__(256)
void agg_out(const int* __restrict__ src_dm, const int* __restrict__ src_am,
             const float* __restrict__ p_rel, float* __restrict__ out) {
    __shared__ float sWc[128 * 8];
    __shared__ float sc[9];   // [0]=g, [1..8]=cvec
    for (int i = threadIdx.x; i < 1024; i += 256) sWc[i] = d_Wcomb[i];
    if (threadIdx.x < 8) sc[threadIdx.x + 1] = d_cvec[threadIdx.x];
    if (threadIdx.x == 0) sc[0] = d_gs[0];
    __syncthreads();

    int warp = threadIdx.x >> 5, lane = threadIdx.x & 31;
    int node = blockIdx.x * 8 + warp;        // grid is exact: 12500*8 = NM
    int h = lane >> 2;
    const float scale = 0.25f;               // 1/sqrt(16)
    float p0 = p_rel[h] * scale;             // relation 0 (director->movie)
    float p1 = p_rel[8 + h] * scale;         // relation 1 (actor->movie)

    float4 qv = *(const float4*)&d_q0[(size_t)node * 128 + lane * 4];
    int beg = d_rowptr[node], end = d_rowptr[node + 1];

    float4 acc = make_float4(0.f, 0.f, 0.f, 0.f);
    float den = 0.f;
    for (int i = beg; i < end; i++) {
        int ge = d_eidx[i];
        const float* ktb; const float* mtb; int src; float ph;
        if (ge < E0) { src = src_dm[ge];      ktb = d_ktdm; mtb = d_mtdm; ph = p0; }
        else         { src = src_am[ge - E0]; ktb = d_ktam; mtb = d_mtam; ph = p1; }
        size_t base = (size_t)src * 128 + lane * 4;
        float4 kt = *(const float4*)(ktb + base);
        float4 mt = *(const float4*)(mtb + base);
        float part = qv.x * kt.x + qv.y * kt.y + qv.z * kt.z + qv.w * kt.w;
        part += __shfl_xor_sync(0xffffffffu, part, 1);
        part += __shfl_xor_sync(0xffffffffu, part, 2);   // head-local dot (4 lanes)
        float a = expf(part * ph);
        den += a;
        acc.x += a * mt.x; acc.y += a * mt.y; acc.z += a * mt.z; acc.w += a * mt.w;
    }
    float inv = (den > 0.f) ? (1.f / den) : 0.f;
    float gl[4];
    gl[0] = gelu_exact(acc.x * inv);
    gl[1] = gelu_exact(acc.y * inv);
    gl[2] = gelu_exact(acc.z * inv);
    gl[3] = gelu_exact(acc.w * inv);

    float o[8] = {0, 0, 0, 0, 0, 0, 0, 0};
    int r0 = lane * 4;
#pragma unroll
    for (int j = 0; j < 4; j++) {
        float gj = gl[j];
        const float* wr = &sWc[(r0 + j) * 8];
#pragma unroll
        for (int c = 0; c < 8; c++) o[c] += gj * wr[c];
    }
#pragma unroll
    for (int off = 16; off > 0; off >>= 1)
#pragma unroll
        for (int c = 0; c < 8; c++) o[c] += __shfl_xor_sync(0xffffffffu, o[c], off);

    if (lane == 0) {
        float g = sc[0];
#pragma unroll
        for (int c = 0; c < 8; c++)
            out[(size_t)node * 8 + c] = g * o[c] + (1.f - g) * d_s0[(size_t)node * 8 + c] + sc[1 + c];
    }
}

// ---------------- launch ----------------
#define SYM(p, s) cudaGetSymbolAddress((void**)&(p), s)

extern "C" void kernel_launch(void* const* d_in, const int* in_sizes, int n_in,
                              void* d_out, int out_size) {
    (void)in_sizes; (void)n_in; (void)out_size;
    const float* x_m   = (const float*)d_in[0];
    const float* x_d   = (const float*)d_in[1];
    const float* x_a   = (const float*)d_in[2];
    const int* src_dm  = (const int*)d_in[3];
    const int* dst_dm  = (const int*)d_in[4];
    const int* src_am  = (const int*)d_in[5];
    const int* dst_am  = (const int*)d_in[6];
    // d_in[7..10]: movie->director / movie->actor edges — dead (output uses movie bucket only)
    const float* Wpre_m = (const float*)d_in[11];
    const float* Wpre_d = (const float*)d_in[12];
    const float* Wpre_a = (const float*)d_in[13];
    const float* bpre   = (const float*)d_in[14];
    const float* Wk     = (const float*)d_in[15];
    const float* bk     = (const float*)d_in[16];
    const float* Wq     = (const float*)d_in[17];
    const float* bq     = (const float*)d_in[18];
    const float* Wv     = (const float*)d_in[19];
    const float* bv     = (const float*)d_in[20];
    const float* a_rel  = (const float*)d_in[21];
    const float* m_rel  = (const float*)d_in[22];
    const float* p_rel  = (const float*)d_in[23];
    const float* skip   = (const float*)d_in[24];
    const float* Wa     = (const float*)d_in[25];
    const float* ba     = (const float*)d_in[26];
    const float* Wlin   = (const float*)d_in[27];
    const float* blin   = (const float*)d_in[28];
    float* out = (float*)d_out;

    float *WeffK0, *WeffV0, *WeffK1, *WeffV1;
    float *beffK0, *beffV0, *beffK1, *beffV1;
    float *WK0, *WV0, *WK1, *WV1, *bK0, *bV0, *bK1, *bV1;
    float *Wqf, *bqf, *Wsf, *bsf, *Wcomb, *tmp8;
    float *q0, *s0, *ktdm, *mtdm, *ktam, *mtam;
    SYM(WeffK0, d_WeffK0); SYM(WeffV0, d_WeffV0); SYM(WeffK1, d_WeffK1); SYM(WeffV1, d_WeffV1);
    SYM(beffK0, d_beffK0); SYM(beffV0, d_beffV0); SYM(beffK1, d_beffK1); SYM(beffV1, d_beffV1);
    SYM(WK0, d_WK0); SYM(WV0, d_WV0); SYM(WK1, d_WK1); SYM(WV1, d_WV1);
    SYM(bK0, d_bK0); SYM(bV0, d_bV0); SYM(bK1, d_bK1); SYM(bV1, d_bV1);
    SYM(Wqf, d_Wqf); SYM(bqf, d_bqf); SYM(Wsf, d_Wsf); SYM(bsf, d_bsf);
    SYM(Wcomb, d_Wcomb); SYM(tmp8, d_tmp8);
    SYM(q0, d_q0); SYM(s0, d_s0);
    SYM(ktdm, d_ktdm); SYM(mtdm, d_mtdm); SYM(ktam, d_ktam); SYM(mtam, d_mtam);

    // 1) block-diagonal relation composes:  Weff = Wk/v[st] @ BD(a/m_rel[r])
    bd_compose<<<129, 128>>>(Wk + 16384, bk + 128, a_rel,        WeffK0, beffK0); // r0: director keys
    bd_compose<<<129, 128>>>(Wk + 32768, bk + 256, a_rel + 2048, WeffK1, beffK1); // r1: actor keys
    bd_compose<<<129, 128>>>(Wv + 16384, bv + 128, m_rel,        WeffV0, beffV0); // r0: director msgs
    bd_compose<<<129, 128>>>(Wv + 32768, bv + 256, m_rel + 2048, WeffV1, beffV1); // r1: actor msgs

    // 2) fold pre-encoder into everything (x @ Wfull + bfull directly from raw features)
    smallmm<<<64, 256>>>(Wpre_d, WeffK0, nullptr, WK0, 128, 128, 128);
    smallmm<<<1, 128>>>(bpre + 128, WeffK0, beffK0, bK0, 1, 128, 128);
    smallmm<<<64, 256>>>(Wpre_d, WeffV0, nullptr, WV0, 128, 128, 128);
    smallmm<<<1, 128>>>(bpre + 128, WeffV0, beffV0, bV0, 1, 128, 128);
    smallmm<<<64, 256>>>(Wpre_a, WeffK1, nullptr, WK1, 128, 128, 128);
    smallmm<<<1, 128>>>(bpre + 256, WeffK1, beffK1, bK1, 1, 128, 128);
    smallmm<<<64, 256>>>(Wpre_a, WeffV1, nullptr, WV1, 128, 128, 128);
    smallmm<<<1, 128>>>(bpre + 256, WeffV1, beffV1, bV1, 1, 128, 128);
    smallmm<<<128, 256>>>(Wpre_m, Wq, nullptr, Wqf, 256, 128, 128);
    smallmm<<<1, 128>>>(bpre, Wq, bq, bqf, 1, 128, 128);
    smallmm<<<8, 256>>>(Wpre_m, Wlin, nullptr, Wsf, 256, 128, 8);
    smallmm<<<1, 32>>>(bpre, Wlin, nullptr, bsf, 1, 128, 8);
    smallmm<<<4, 256>>>(Wa, Wlin, nullptr, Wcomb, 128, 128, 8);
    smallmm<<<1, 32>>>(ba, Wlin, nullptr, tmp8, 1, 128, 8);
    make_consts<<<1, 32>>>(skip, blin);

    // 3) node-level GEMMs (the heavy part this round)
    gemm_f32<<<782, 256>>>(x_m, Wqf, bqf, q0, NM, 256);   // movie queries
    kernel_s0<<<12500, 256>>>(x_m, Wsf, bsf, s0, NM);     // skip-path xs0@Wlin
    gemm_f32<<<157, 256>>>(x_d, WK0, bK0, ktdm, ND, 128); // director keys (rel-transformed)
    gemm_f32<<<157, 256>>>(x_d, WV0, bV0, mtdm, ND, 128); // director messages
    gemm_f32<<<391, 256>>>(x_a, WK1, bK1, ktam, NA, 128); // actor keys
    gemm_f32<<<391, 256>>>(x_a, WV1, bV1, mtam, NA, 128); // actor messages

    // 4) CSR by destination movie node
    zero_counts<<<391, 256>>>();
    count_edges<<<2344, 256>>>(dst_dm, dst_am);
    scan_block<<<NB, 1024>>>();
    scan_bsum<<<1, 32>>>();
    add_offsets<<<391, 256>>>();
    fill_edges<<<2344, 256>>>(dst_dm, dst_am);

    // 5) fused attention + softmax aggregation + gelu + output head
    agg_out<<<12500, 256>>>(src_dm, src_am, p_rel, out);
}

// round 2
// speedup vs baseline: 1.5563x; 1.5563x over previous
#include <cuda_runtime.h>
#include <math.h>
#include <stdint.h>

#define NM 100000
#define ND 20000
#define NA 50000
#define E0 300000
#define ETOT 600000
#define NB 98   // ceil(NM/1024)

// ---------------- scratch (static device memory; no allocs) ----------------
__device__ float d_q0[NM * 128];
__device__ float d_s0[NM * 8];
__device__ float d_ktdm[ND * 128];
__device__ float d_mtdm[ND * 128];
__device__ float d_ktam[NA * 128];
__device__ float d_mtam[NA * 128];
__device__ int   d_counts[NM];
__device__ int   d_cursor[NM];
__device__ int   d_rowptr[NM + 1];
__device__ int   d_bsum[128];
__device__ int   d_eidx[ETOT];

__device__ float d_WeffK0[128 * 128], d_WeffV0[128 * 128];
__device__ float d_WeffK1[128 * 128], d_WeffV1[128 * 128];
__device__ float d_beffK0[128], d_beffV0[128], d_beffK1[128], d_beffV1[128];
__device__ float d_WK0[128 * 128], d_WV0[128 * 128], d_WK1[128 * 128], d_WV1[128 * 128];
__device__ float d_bK0[128], d_bV0[128], d_bK1[128], d_bV1[128];
__device__ float d_Wqf[256 * 128];
__device__ float d_bqf[128];
__device__ float d_Wsf[256 * 8];
__device__ float d_bsf[8];
__device__ float d_Wcomb[128 * 8];
__device__ float d_tmp8[8];

// ---------------- fused weight-composition kernels ----------------

// All 4 block-diagonal composes in one launch.
// blockIdx.x = which*129 + i ; i==128 composes the bias row.
__global__ void prep_compose(const float* __restrict__ Wk, const float* __restrict__ bk,
                             const float* __restrict__ Wv, const float* __restrict__ bv,
                             const float* __restrict__ a_rel, const float* __restrict__ m_rel) {
    int which = blockIdx.x / 129;
    int i = blockIdx.x - which * 129;
    const float *Win, *bin, *A; float *Weff, *beff;
    switch (which) {
        case 0: Win = Wk + 16384; bin = bk + 128; A = a_rel;        Weff = d_WeffK0; beff = d_beffK0; break;
        case 1: Win = Wk + 32768; bin = bk + 256; A = a_rel + 2048; Weff = d_WeffK1; beff = d_beffK1; break;
        case 2: Win = Wv + 16384; bin = bv + 128; A = m_rel;        Weff = d_WeffV0; beff = d_beffV0; break;
        default:Win = Wv + 32768; bin = bv + 256; A = m_rel + 2048; Weff = d_WeffV1; beff = d_beffV1; break;
    }
    int col = threadIdx.x;               // 0..127
    int h = col >> 4, f = col & 15;
    const float* arow = A + h * 256 + f; // A[h][d][f], stride 16 over d
    const float* w = (i < 128) ? (Win + i * 128 + h * 16) : (bin + h * 16);
    float s = 0.f;
#pragma unroll
    for (int d = 0; d < 16; d++) s += w[d] * arow[d * 16];
    if (i < 128) Weff[i * 128 + col] = s;
    else         beff[col] = s;
}

__device__ __forceinline__ void mm_task(const float* __restrict__ A, const float* __restrict__ B,
                                        const float* __restrict__ add, float* __restrict__ C,
                                        int M, int K, int N, int t) {
    if (t >= M * N) return;
    int m = t / N, n = t - m * N;
    float s = add ? add[n] : 0.f;
    for (int k = 0; k < K; k++) s += A[m * K + k] * B[k * N + n];
    C[t] = s;
}

// All small weight-chain matmuls in one launch (403 blocks x 256).
__global__ void prep_mm(const float* __restrict__ Wpre_m, const float* __restrict__ Wpre_d,
                        const float* __restrict__ Wpre_a, const float* __restrict__ bpre,
                        const float* __restrict__ Wq, const float* __restrict__ bq,
                        const float* __restrict__ Wa, const float* __restrict__ ba,
                        const float* __restrict__ Wlin) {
    int b = blockIdx.x;
    int tid = threadIdx.x;
    if (b < 64)        mm_task(Wpre_d, d_WeffK0, nullptr, d_WK0, 128, 128, 128, b * 256 + tid);
    else if (b < 128)  mm_task(Wpre_d, d_WeffV0, nullptr, d_WV0, 128, 128, 128, (b - 64) * 256 + tid);
    else if (b < 192)  mm_task(Wpre_a, d_WeffK1, nullptr, d_WK1, 128, 128, 128, (b - 128) * 256 + tid);
    else if (b < 256)  mm_task(Wpre_a, d_WeffV1, nullptr, d_WV1, 128, 128, 128, (b - 192) * 256 + tid);
    else if (b < 384)  mm_task(Wpre_m, Wq, nullptr, d_Wqf, 256, 128, 128, (b - 256) * 256 + tid);
    else if (b == 384) mm_task(bpre + 128, d_WeffK0, d_beffK0, d_bK0, 1, 128, 128, tid);
    else if (b == 385) mm_task(bpre + 128, d_WeffV0, d_beffV0, d_bV0, 1, 128, 128, tid);
    else if (b == 386) mm_task(bpre + 256, d_WeffK1, d_beffK1, d_bK1, 1, 128, 128, tid);
    else if (b == 387) mm_task(bpre + 256, d_WeffV1, d_beffV1, d_bV1, 1, 128, 128, tid);
    else if (b == 388) mm_task(bpre, Wq, bq, d_bqf, 1, 128, 128, tid);
    else if (b < 397)  mm_task(Wpre_m, Wlin, nullptr, d_Wsf, 256, 128, 8, (b - 389) * 256 + tid);
    else if (b == 397) mm_task(bpre, Wlin, nullptr, d_bsf, 1, 128, 8, tid);
    else if (b < 402)  mm_task(Wa, Wlin, nullptr, d_Wcomb, 128, 128, 8, (b - 398) * 256 + tid);
    else               mm_task(ba, Wlin, nullptr, d_tmp8, 1, 128, 8, tid);
}

// ---------------- tf32 tensor-core GEMM: C[M x 128] = A[M x K] @ W[K x 128] + bias ----------------
__device__ __forceinline__ uint32_t f2tf32(float x) {
    uint32_t r;
    asm("cvt.rna.tf32.f32 %0, %1;" : "=r"(r) : "f"(x));
    return r;
}

__global__ __launch_bounds__(256, 2)
void gemm_tf32(const float* __restrict__ A, const float* __restrict__ W,
               const float* __restrict__ bias, float* __restrict__ C,
               int M, int K) {
    __shared__ float As[32][129];   // As[k][row]  (stride 129 -> conflict-free STS/LDS)
    __shared__ float Bs[32][136];   // Bs[k][col]  (stride 136 -> conflict-free frag LDS)

    int tid = threadIdx.x;
    int row0 = blockIdx.x * 128;
    int warp = tid >> 5, lane = tid & 31;
    int wm = warp >> 1, wn = warp & 1;    // warp grid 4(M) x 2(N): warp tile 32x64
    int g = lane >> 2, tg = lane & 3;

    float acc[2][8][4];
#pragma unroll
    for (int mi = 0; mi < 2; mi++)
#pragma unroll
        for (int ni = 0; ni < 8; ni++)
#pragma unroll
            for (int c = 0; c < 4; c++) acc[mi][ni][c] = 0.f;

    for (int k0 = 0; k0 < K; k0 += 32) {
        // A tile: 128 rows x 32 k, transposed into As[k][row]
#pragma unroll
        for (int l = 0; l < 4; l++) {
            int fidx = tid + l * 256;            // 0..1023 float4s
            int r = fidx >> 3;                   // 0..127
            int kq = (fidx & 7) * 4;             // 0..28
            int gr = row0 + r;
            float4 v = make_float4(0.f, 0.f, 0.f, 0.f);
            if (gr < M) v = *(const float4*)&A[(size_t)gr * K + k0 + kq];
            As[kq + 0][r] = __uint_as_float(f2tf32(v.x));
            As[kq + 1][r] = __uint_as_float(f2tf32(v.y));
            As[kq + 2][r] = __uint_as_float(f2tf32(v.z));
            As[kq + 3][r] = __uint_as_float(f2tf32(v.w));
        }
        // W tile: 32 k x 128 cols, natural layout
#pragma unroll
        for (int l = 0; l < 4; l++) {
            int fidx = tid + l * 256;
            int kk = fidx >> 5;
            int c4 = (fidx & 31) * 4;
            float4 v = *(const float4*)&W[(size_t)(k0 + kk) * 128 + c4];
            float4 t;
            t.x = __uint_as_float(f2tf32(v.x));
            t.y = __uint_as_float(f2tf32(v.y));
            t.z = __uint_as_float(f2tf32(v.z));
            t.w = __uint_as_float(f2tf32(v.w));
            *(float4*)&Bs[kk][c4] = t;
        }
        __syncthreads();

#pragma unroll
        for (int ks = 0; ks < 32; ks += 8) {
            uint32_t a[2][4];
#pragma unroll
            for (int mi = 0; mi < 2; mi++) {
                int ar = wm * 32 + mi * 16 + g;
                a[mi][0] = __float_as_uint(As[ks + tg][ar]);
                a[mi][1] = __float_as_uint(As[ks + tg][ar + 8]);
                a[mi][2] = __float_as_uint(As[ks + tg + 4][ar]);
                a[mi][3] = __float_as_uint(As[ks + tg + 4][ar + 8]);
            }
#pragma unroll
            for (int ni = 0; ni < 8; ni++) {
                int bc = wn * 64 + ni * 8 + g;
                uint32_t b0 = __float_as_uint(Bs[ks + tg][bc]);
                uint32_t b1 = __float_as_uint(Bs[ks + tg + 4][bc]);
#pragma unroll
                for (int mi = 0; mi < 2; mi++) {
                    asm volatile(
                        "mma.sync.aligned.m16n8k8.row.col.f32.tf32.tf32.f32 "
                        "{%0,%1,%2,%3}, {%4,%5,%6,%7}, {%8,%9}, {%0,%1,%2,%3};"
                        : "+f"(acc[mi][ni][0]), "+f"(acc[mi][ni][1]),
                          "+f"(acc[mi][ni][2]), "+f"(acc[mi][ni][3])
                        : "r"(a[mi][0]), "r"(a[mi][1]), "r"(a[mi][2]), "r"(a[mi][3]),
                          "r"(b0), "r"(b1));
                }
            }
        }
        __syncthreads();
    }

    // epilogue: c0,c1 -> (row=g, col=2*tg, 2*tg+1); c2,c3 -> row+8
#pragma unroll
    for (int mi = 0; mi < 2; mi++) {
#pragma unroll
        for (int ni = 0; ni < 8; ni++) {
            int col = wn * 64 + ni * 8 + tg * 2;
            float bx = bias[col], by = bias[col + 1];
            int r1 = row0 + wm * 32 + mi * 16 + g;
            if (r1 < M) {
                float2 o = make_float2(acc[mi][ni][0] + bx, acc[mi][ni][1] + by);
                *(float2*)&C[(size_t)r1 * 128 + col] = o;
            }
            int r2 = r1 + 8;
            if (r2 < M) {
                float2 o = make_float2(acc[mi][ni][2] + bx, acc[mi][ni][3] + by);
                *(float2*)&C[(size_t)r2 * 128 + col] = o;
            }
        }
    }
}

// ---------------- thin GEMM for skip path: s0[M x 8] = A[M x 256] @ W[256 x 8] + bias ----------------
__global__ void kernel_s0(const float* __restrict__ A, const float* __restrict__ W,
                          const float* __restrict__ bias, float* __restrict__ C, int M) {
    __shared__ float sW[2048];
    for (int i = threadIdx.x; i < 2048; i += 256) sW[i] = W[i];
    __syncthreads();
    int gw = (blockIdx.x * 256 + threadIdx.x) >> 5;
    int lane = threadIdx.x & 31;
    if (gw >= M) return;
    const float4* a = (const float4*)(A + (size_t)gw * 256);
    float4 v0 = a[lane];
    float4 v1 = a[lane + 32];
    float av[8] = {v0.x, v0.y, v0.z, v0.w, v1.x, v1.y, v1.z, v1.w};
    float o[8] = {0, 0, 0, 0, 0, 0, 0, 0};
    int k0 = lane * 4;
#pragma unroll
    for (int j = 0; j < 8; j++) {
        int k = (j < 4) ? (k0 + j) : (128 + k0 + j - 4);
        const float* wr = &sW[k * 8];
#pragma unroll
        for (int c = 0; c < 8; c++) o[c] += av[j] * wr[c];
    }
#pragma unroll
    for (int off = 16; off > 0; off >>= 1)
#pragma unroll
        for (int c = 0; c < 8; c++) o[c] += __shfl_xor_sync(0xffffffffu, o[c], off);
    if (lane == 0) {
#pragma unroll
        for (int c = 0; c < 8; c++) C[(size_t)gw * 8 + c] = o[c] + bias[c];
    }
}

// ---------------- CSR build (counting sort by destination movie node) ----------------
__global__ void zero_counts() {
    int i = blockIdx.x * blockDim.x + threadIdx.x;
    if (i < NM) d_counts[i] = 0;
}
__global__ void count_edges(const int* __restrict__ dst_dm, const int* __restrict__ dst_am) {
    int e = blockIdx.x * blockDim.x + threadIdx.x;
    if (e < E0) atomicAdd(&d_counts[dst_dm[e]], 1);
    else if (e < ETOT) atomicAdd(&d_counts[dst_am[e - E0]], 1);
}
__global__ void scan_block() {   // 1024 threads/block, NB blocks
    __shared__ int sh[1024];
    int i = blockIdx.x * 1024 + threadIdx.x;
    int v = (i < NM) ? d_counts[i] : 0;
    sh[threadIdx.x] = v;
    __syncthreads();
    for (int off = 1; off < 1024; off <<= 1) {
        int t = (threadIdx.x >= off) ? sh[threadIdx.x - off] : 0;
        __syncthreads();
        sh[threadIdx.x] += t;
        __syncthreads();
    }
    if (i < NM) d_rowptr[i] = sh[threadIdx.x] - v;   // exclusive
    if (threadIdx.x == 1023) d_bsum[blockIdx.x] = sh[1023];
}
__global__ void scan_bsum() {
    if (threadIdx.x == 0) {
        int s = 0;
        for (int b = 0; b < NB; b++) { int v = d_bsum[b]; d_bsum[b] = s; s += v; }
    }
}
__global__ void add_offsets() {
    int i = blockIdx.x * blockDim.x + threadIdx.x;
    if (i < NM) {
        int v = d_rowptr[i] + d_bsum[i >> 10];
        d_rowptr[i] = v;
        d_cursor[i] = v;
    }
    if (i == 0) d_rowptr[NM] = ETOT;
}
__global__ void fill_edges(const int* __restrict__ dst_dm, const int* __restrict__ dst_am) {
    int e = blockIdx.x * blockDim.x + threadIdx.x;
    int d;
    if (e < E0) d = dst_dm[e];
    else if (e < ETOT) d = dst_am[e - E0];
    else return;
    int pos = atomicAdd(&d_cursor[d], 1);
    d_eidx[pos] = e;   // global edge id: [0,E0)=rel0(dm), [E0,2E0)=rel1(am)
}

// ---------------- fused: per-edge attention + softmax-agg + gelu + output head ----------------
__device__ __forceinline__ float gelu_exact(float x) { return x * normcdff(x); }

__global__ __launch_bounds__(256)
void agg_out(const int* __restrict__ src_dm, const int* __restrict__ src_am,
             const float* __restrict__ p_rel, const float* __restrict__ skip,
             const float* __restrict__ blin, float* __restrict__ out) {
    __shared__ float sWc[128 * 8];
    __shared__ float sc[9];   // [0]=g, [1..8]=cvec
    for (int i = threadIdx.x; i < 1024; i += 256) sWc[i] = d_Wcomb[i];
    if (threadIdx.x < 8) {
        float gg = 1.f / (1.f + expf(-skip[0]));
        sc[1 + threadIdx.x] = gg * d_tmp8[threadIdx.x] + blin[threadIdx.x];
        if (threadIdx.x == 0) sc[0] = gg;
    }
    __syncthreads();

    int warp = threadIdx.x >> 5, lane = threadIdx.x & 31;
    int node = blockIdx.x * 8 + warp;        // grid exact: 12500*8 = NM
    int h = lane >> 2;
    const float scale = 0.25f;               // 1/sqrt(16)
    float p0 = p_rel[h] * scale;             // rel 0 (director->movie)
    float p1 = p_rel[8 + h] * scale;         // rel 1 (actor->movie)

    float4 qv = *(const float4*)&d_q0[(size_t)node * 128 + lane * 4];
    int beg = d_rowptr[node], end = d_rowptr[node + 1];

    float4 acc = make_float4(0.f, 0.f, 0.f, 0.f);
    float den = 0.f;
    for (int i = beg; i < end; i++) {
        int ge = d_eidx[i];
        const float* ktb; const float* mtb; int src; float ph;
        if (ge < E0) { src = src_dm[ge];      ktb = d_ktdm; mtb = d_mtdm; ph = p0; }
        else         { src = src_am[ge - E0]; ktb = d_ktam; mtb = d_mtam; ph = p1; }
        size_t base = (size_t)src * 128 + lane * 4;
        float4 kt = *(const float4*)(ktb + base);
        float4 mt = *(const float4*)(mtb + base);
        float part = qv.x * kt.x + qv.y * kt.y + qv.z * kt.z + qv.w * kt.w;
        part += __shfl_xor_sync(0xffffffffu, part, 1);
        part += __shfl_xor_sync(0xffffffffu, part, 2);   // head-local dot (4 lanes)
        float a = expf(part * ph);
        den += a;
        acc.x += a * mt.x; acc.y += a * mt.y; acc.z += a * mt.z; acc.w += a * mt.w;
    }
    float inv = (den > 0.f) ? (1.f / den) : 0.f;
    float gl[4];
    gl[0] = gelu_exact(acc.x * inv);
    gl[1] = gelu_exact(acc.y * inv);
    gl[2] = gelu_exact(acc.z * inv);
    gl[3] = gelu_exact(acc.w * inv);

    float o[8] = {0, 0, 0, 0, 0, 0, 0, 0};
    int r0 = lane * 4;
#pragma unroll
    for (int j = 0; j < 4; j++) {
        float gj = gl[j];
        const float* wr = &sWc[(r0 + j) * 8];
#pragma unroll
        for (int c = 0; c < 8; c++) o[c] += gj * wr[c];
    }
#pragma unroll
    for (int off = 16; off > 0; off >>= 1)
#pragma unroll
        for (int c = 0; c < 8; c++) o[c] += __shfl_xor_sync(0xffffffffu, o[c], off);

    if (lane == 0) {
        float g = sc[0];
#pragma unroll
        for (int c = 0; c < 8; c++)
            out[(size_t)node * 8 + c] = g * o[c] + (1.f - g) * d_s0[(size_t)node * 8 + c] + sc[1 + c];
    }
}

// ---------------- launch ----------------
#define SYM(p, s) cudaGetSymbolAddress((void**)&(p), s)

extern "C" void kernel_launch(void* const* d_in, const int* in_sizes, int n_in,
                              void* d_out, int out_size) {
    (void)in_sizes; (void)n_in; (void)out_size;
    const float* x_m   = (const float*)d_in[0];
    const float* x_d   = (const float*)d_in[1];
    const float* x_a   = (const float*)d_in[2];
    const int* src_dm  = (const int*)d_in[3];
    const int* dst_dm  = (const int*)d_in[4];
    const int* src_am  = (const int*)d_in[5];
    const int* dst_am  = (const int*)d_in[6];
    // d_in[7..10]: movie->director / movie->actor edges — dead (output uses movie bucket only)
    const float* Wpre_m = (const float*)d_in[11];
    const float* Wpre_d = (const float*)d_in[12];
    const float* Wpre_a = (const float*)d_in[13];
    const float* bpre   = (const float*)d_in[14];
    const float* Wk     = (const float*)d_in[15];
    const float* bk     = (const float*)d_in[16];
    const float* Wq     = (const float*)d_in[17];
    const float* bq     = (const float*)d_in[18];
    const float* Wv     = (const float*)d_in[19];
    const float* bv     = (const float*)d_in[20];
    const float* a_rel  = (const float*)d_in[21];
    const float* m_rel  = (const float*)d_in[22];
    const float* p_rel  = (const float*)d_in[23];
    const float* skip   = (const float*)d_in[24];
    const float* Wa     = (const float*)d_in[25];
    const float* ba     = (const float*)d_in[26];
    const float* Wlin   = (const float*)d_in[27];
    const float* blin   = (const float*)d_in[28];
    float* out = (float*)d_out;

    float *WK0, *WV0, *WK1, *WV1, *bK0, *bV0, *bK1, *bV1;
    float *Wqf, *bqf, *Wsf, *bsf;
    float *q0, *s0, *ktdm, *mtdm, *ktam, *mtam;
    SYM(WK0, d_WK0); SYM(WV0, d_WV0); SYM(WK1, d_WK1); SYM(WV1, d_WV1);
    SYM(bK0, d_bK0); SYM(bV0, d_bV0); SYM(bK1, d_bK1); SYM(bV1, d_bV1);
    SYM(Wqf, d_Wqf); SYM(bqf, d_bqf); SYM(Wsf, d_Wsf); SYM(bsf, d_bsf);
    SYM(q0, d_q0); SYM(s0, d_s0);
    SYM(ktdm, d_ktdm); SYM(mtdm, d_mtdm); SYM(ktam, d_ktam); SYM(mtam, d_mtam);

    // 1) fused weight prep (2 launches)
    prep_compose<<<516, 128>>>(Wk, bk, Wv, bv, a_rel, m_rel);
    prep_mm<<<403, 256>>>(Wpre_m, Wpre_d, Wpre_a, bpre, Wq, bq, Wa, ba, Wlin);

    // 2) node-level GEMMs on tensor cores (tf32)
    gemm_tf32<<<782, 256>>>(x_m, Wqf, bqf, q0, NM, 256);   // movie queries
    kernel_s0<<<12500, 256>>>(x_m, Wsf, bsf, s0, NM);      // skip-path xs0@Wlin
    gemm_tf32<<<157, 256>>>(x_d, WK0, bK0, ktdm, ND, 128); // director keys
    gemm_tf32<<<157, 256>>>(x_d, WV0, bV0, mtdm, ND, 128); // director messages
    gemm_tf32<<<391, 256>>>(x_a, WK1, bK1, ktam, NA, 128); // actor keys
    gemm_tf32<<<391, 256>>>(x_a, WV1, bV1, mtam, NA, 128); // actor messages

    // 3) CSR by destination movie node
    zero_counts<<<391, 256>>>();
    count_edges<<<2344, 256>>>(dst_dm, dst_am);
    scan_block<<<NB, 1024>>>();
    scan_bsum<<<1, 32>>>();
    add_offsets<<<391, 256>>>();
    fill_edges<<<2344, 256>>>(dst_dm, dst_am);

    // 4) fused attention + softmax aggregation + gelu + output head
    agg_out<<<12500, 256>>>(src_dm, src_am, p_rel, skip, blin, out);
}

// round 4
// speedup vs baseline: 2.0846x; 1.3394x over previous
#include <cuda_runtime.h>
#include <math.h>
#include <stdint.h>

#define NM 100000
#define ND 20000
#define NA 50000
#define E0 300000
#define ETOT 600000
#define NB 98   // ceil(NM/1024)

// ---------------- scratch (static device memory; no allocs) ----------------
__device__ float d_q0[NM * 128];
__device__ float d_s0[NM * 8];
__device__ float d_ktdm[ND * 128];
__device__ float d_mtdm[ND * 128];
__device__ float d_ktam[NA * 128];
__device__ float d_mtam[NA * 128];
__device__ int   d_counts[NM];
__device__ int   d_cursor[NM];
__device__ int   d_rowptr[NM + 1];
__device__ int   d_bsum[128];
__device__ int   d_epay[ETOT];   // packed: src | (rel<<31)

__device__ float d_WeffK0[128 * 128], d_WeffV0[128 * 128];
__device__ float d_WeffK1[128 * 128], d_WeffV1[128 * 128];
__device__ float d_beffK0[128], d_beffV0[128], d_beffK1[128], d_beffV1[128];
__device__ float d_WK0[128 * 128], d_WV0[128 * 128], d_WK1[128 * 128], d_WV1[128 * 128];
__device__ float d_bK0[128], d_bV0[128], d_bK1[128], d_bV1[128];
__device__ float d_Wqf[256 * 128];
__device__ float d_bqf[128];
__device__ float d_Wsf[256 * 8];
__device__ float d_bsf[8];
__device__ float d_Wcomb[128 * 8];
__device__ float d_tmp8[8];

// ---------------- fused weight-composition kernels ----------------

__global__ void prep_compose(const float* __restrict__ Wk, const float* __restrict__ bk,
                             const float* __restrict__ Wv, const float* __restrict__ bv,
                             const float* __restrict__ a_rel, const float* __restrict__ m_rel) {
    int which = blockIdx.x / 129;
    int i = blockIdx.x - which * 129;
    const float *Win, *bin, *A; float *Weff, *beff;
    switch (which) {
        case 0: Win = Wk + 16384; bin = bk + 128; A = a_rel;        Weff = d_WeffK0; beff = d_beffK0; break;
        case 1: Win = Wk + 32768; bin = bk + 256; A = a_rel + 2048; Weff = d_WeffK1; beff = d_beffK1; break;
        case 2: Win = Wv + 16384; bin = bv + 128; A = m_rel;        Weff = d_WeffV0; beff = d_beffV0; break;
        default:Win = Wv + 32768; bin = bv + 256; A = m_rel + 2048; Weff = d_WeffV1; beff = d_beffV1; break;
    }
    int col = threadIdx.x;               // 0..127
    int h = col >> 4, f = col & 15;
    const float* arow = A + h * 256 + f; // A[h][d][f], stride 16 over d
    const float* w = (i < 128) ? (Win + i * 128 + h * 16) : (bin + h * 16);
    float s = 0.f;
#pragma unroll
    for (int d = 0; d < 16; d++) s += w[d] * arow[d * 16];
    if (i < 128) Weff[i * 128 + col] = s;
    else         beff[col] = s;
}

__device__ __forceinline__ void mm_task(const float* __restrict__ A, const float* __restrict__ B,
                                        const float* __restrict__ add, float* __restrict__ C,
                                        int M, int K, int N, int t) {
    if (t >= M * N) return;
    int m = t / N, n = t - m * N;
    float s = add ? add[n] : 0.f;
    for (int k = 0; k < K; k++) s += A[m * K + k] * B[k * N + n];
    C[t] = s;
}

__global__ void prep_mm(const float* __restrict__ Wpre_m, const float* __restrict__ Wpre_d,
                        const float* __restrict__ Wpre_a, const float* __restrict__ bpre,
                        const float* __restrict__ Wq, const float* __restrict__ bq,
                        const float* __restrict__ Wa, const float* __restrict__ ba,
                        const float* __restrict__ Wlin) {
    int b = blockIdx.x;
    int tid = threadIdx.x;
    if (b < 64)        mm_task(Wpre_d, d_WeffK0, nullptr, d_WK0, 128, 128, 128, b * 256 + tid);
    else if (b < 128)  mm_task(Wpre_d, d_WeffV0, nullptr, d_WV0, 128, 128, 128, (b - 64) * 256 + tid);
    else if (b < 192)  mm_task(Wpre_a, d_WeffK1, nullptr, d_WK1, 128, 128, 128, (b - 128) * 256 + tid);
    else if (b < 256)  mm_task(Wpre_a, d_WeffV1, nullptr, d_WV1, 128, 128, 128, (b - 192) * 256 + tid);
    else if (b < 384)  mm_task(Wpre_m, Wq, nullptr, d_Wqf, 256, 128, 128, (b - 256) * 256 + tid);
    else if (b == 384) mm_task(bpre + 128, d_WeffK0, d_beffK0, d_bK0, 1, 128, 128, tid);
    else if (b == 385) mm_task(bpre + 128, d_WeffV0, d_beffV0, d_bV0, 1, 128, 128, tid);
    else if (b == 386) mm_task(bpre + 256, d_WeffK1, d_beffK1, d_bK1, 1, 128, 128, tid);
    else if (b == 387) mm_task(bpre + 256, d_WeffV1, d_beffV1, d_bV1, 1, 128, 128, tid);
    else if (b == 388) mm_task(bpre, Wq, bq, d_bqf, 1, 128, 128, tid);
    else if (b < 397)  mm_task(Wpre_m, Wlin, nullptr, d_Wsf, 256, 128, 8, (b - 389) * 256 + tid);
    else if (b == 397) mm_task(bpre, Wlin, nullptr, d_bsf, 1, 128, 8, tid);
    else if (b < 402)  mm_task(Wa, Wlin, nullptr, d_Wcomb, 128, 128, 8, (b - 398) * 256 + tid);
    else               mm_task(ba, Wlin, nullptr, d_tmp8, 1, 128, 8, tid);
}

// ---------------- tf32 tensor-core GEMM: C[M x 128] = A[M x K] @ W[K x 128] + bias ----------------
__device__ __forceinline__ uint32_t f2tf32(float x) {
    uint32_t r;
    asm("cvt.rna.tf32.f32 %0, %1;" : "=r"(r) : "f"(x));
    return r;
}

__global__ __launch_bounds__(256, 2)
void gemm_tf32(const float* __restrict__ A, const float* __restrict__ W,
               const float* __restrict__ bias, float* __restrict__ C,
               int M, int K) {
    __shared__ float As[32][129];   // As[k][row]
    __shared__ float Bs[32][136];   // Bs[k][col]

    int tid = threadIdx.x;
    int row0 = blockIdx.x * 128;
    int warp = tid >> 5, lane = tid & 31;
    int wm = warp >> 1, wn = warp & 1;    // warp grid 4(M) x 2(N)
    int g = lane >> 2, tg = lane & 3;

    float acc[2][8][4];
#pragma unroll
    for (int mi = 0; mi < 2; mi++)
#pragma unroll
        for (int ni = 0; ni < 8; ni++)
#pragma unroll
            for (int c = 0; c < 4; c++) acc[mi][ni][c] = 0.f;

    for (int k0 = 0; k0 < K; k0 += 32) {
#pragma unroll
        for (int l = 0; l < 4; l++) {
            int fidx = tid + l * 256;
            int r = fidx >> 3;
            int kq = (fidx & 7) * 4;
            int gr = row0 + r;
            float4 v = make_float4(0.f, 0.f, 0.f, 0.f);
            if (gr < M) v = *(const float4*)&A[(size_t)gr * K + k0 + kq];
            As[kq + 0][r] = __uint_as_float(f2tf32(v.x));
            As[kq + 1][r] = __uint_as_float(f2tf32(v.y));
            As[kq + 2][r] = __uint_as_float(f2tf32(v.z));
            As[kq + 3][r] = __uint_as_float(f2tf32(v.w));
        }
#pragma unroll
        for (int l = 0; l < 4; l++) {
            int fidx = tid + l * 256;
            int kk = fidx >> 5;
            int c4 = (fidx & 31) * 4;
            float4 v = *(const float4*)&W[(size_t)(k0 + kk) * 128 + c4];
            float4 t;
            t.x = __uint_as_float(f2tf32(v.x));
            t.y = __uint_as_float(f2tf32(v.y));
            t.z = __uint_as_float(f2tf32(v.z));
            t.w = __uint_as_float(f2tf32(v.w));
            *(float4*)&Bs[kk][c4] = t;
        }
        __syncthreads();

#pragma unroll
        for (int ks = 0; ks < 32; ks += 8) {
            uint32_t a[2][4];
#pragma unroll
            for (int mi = 0; mi < 2; mi++) {
                int ar = wm * 32 + mi * 16 + g;
                a[mi][0] = __float_as_uint(As[ks + tg][ar]);
                a[mi][1] = __float_as_uint(As[ks + tg][ar + 8]);
                a[mi][2] = __float_as_uint(As[ks + tg + 4][ar]);
                a[mi][3] = __float_as_uint(As[ks + tg + 4][ar + 8]);
            }
#pragma unroll
            for (int ni = 0; ni < 8; ni++) {
                int bc = wn * 64 + ni * 8 + g;
                uint32_t b0 = __float_as_uint(Bs[ks + tg][bc]);
                uint32_t b1 = __float_as_uint(Bs[ks + tg + 4][bc]);
#pragma unroll
                for (int mi = 0; mi < 2; mi++) {
                    asm volatile(
                        "mma.sync.aligned.m16n8k8.row.col.f32.tf32.tf32.f32 "
                        "{%0,%1,%2,%3}, {%4,%5,%6,%7}, {%8,%9}, {%0,%1,%2,%3};"
                        : "+f"(acc[mi][ni][0]), "+f"(acc[mi][ni][1]),
                          "+f"(acc[mi][ni][2]), "+f"(acc[mi][ni][3])
                        : "r"(a[mi][0]), "r"(a[mi][1]), "r"(a[mi][2]), "r"(a[mi][3]),
                          "r"(b0), "r"(b1));
                }
            }
        }
        __syncthreads();
    }

#pragma unroll
    for (int mi = 0; mi < 2; mi++) {
#pragma unroll
        for (int ni = 0; ni < 8; ni++) {
            int col = wn * 64 + ni * 8 + tg * 2;
            float bx = bias[col], by = bias[col + 1];
            int r1 = row0 + wm * 32 + mi * 16 + g;
            if (r1 < M) {
                float2 o = make_float2(acc[mi][ni][0] + bx, acc[mi][ni][1] + by);
                *(float2*)&C[(size_t)r1 * 128 + col] = o;
            }
            int r2 = r1 + 8;
            if (r2 < M) {
                float2 o = make_float2(acc[mi][ni][2] + bx, acc[mi][ni][3] + by);
                *(float2*)&C[(size_t)r2 * 128 + col] = o;
            }
        }
    }
}

// ---------------- thin GEMM for skip path: s0[M x 8] = A[M x 256] @ W[256 x 8] + bias ----------
// Conflict-free: W in smem with row stride 9 (9 coprime 32 => bank = (9*lane+c)%32 all distinct
// for k = lane + 32t). One warp per row; 64 LDS + 64 FMA + reduction per row.
__global__ __launch_bounds__(256)
void kernel_s0(const float* __restrict__ A, const float* __restrict__ W,
               const float* __restrict__ bias, float* __restrict__ C, int M) {
    __shared__ float sW[256 * 9];
    for (int i = threadIdx.x; i < 2048; i += 256) {
        int k = i >> 3, c = i & 7;
        sW[k * 9 + c] = W[i];
    }
    __syncthreads();
    int gw = (blockIdx.x * 256 + threadIdx.x) >> 5;
    int lane = threadIdx.x & 31;
    if (gw >= M) return;
    const float* a = A + (size_t)gw * 256;
    float o[8] = {0, 0, 0, 0, 0, 0, 0, 0};
#pragma unroll
    for (int t = 0; t < 8; t++) {
        int k = lane + 32 * t;
        float av = __ldg(&a[k]);
        const float* wr = &sW[k * 9];
#pragma unroll
        for (int c = 0; c < 8; c++) o[c] += av * wr[c];
    }
#pragma unroll
    for (int off = 16; off > 0; off >>= 1)
#pragma unroll
        for (int c = 0; c < 8; c++) o[c] += __shfl_xor_sync(0xffffffffu, o[c], off);
    if (lane == 0) {
#pragma unroll
        for (int c = 0; c < 8; c++) C[(size_t)gw * 8 + c] = o[c] + bias[c];
    }
}

// ---------------- CSR build (counting sort by destination movie node) ----------------
__global__ void count_edges(const int* __restrict__ dst_dm, const int* __restrict__ dst_am) {
    int e = blockIdx.x * blockDim.x + threadIdx.x;
    if (e < E0) atomicAdd(&d_counts[dst_dm[e]], 1);
    else if (e < ETOT) atomicAdd(&d_counts[dst_am[e - E0]], 1);
}
__global__ void scan_block() {   // 1024 threads/block, NB blocks
    __shared__ int sh[1024];
    int i = blockIdx.x * 1024 + threadIdx.x;
    int v = (i < NM) ? d_counts[i] : 0;
    sh[threadIdx.x] = v;
    __syncthreads();
    for (int off = 1; off < 1024; off <<= 1) {
        int t = (threadIdx.x >= off) ? sh[threadIdx.x - off] : 0;
        __syncthreads();
        sh[threadIdx.x] += t;
        __syncthreads();
    }
    if (i < NM) d_rowptr[i] = sh[threadIdx.x] - v;   // exclusive
    if (threadIdx.x == 1023) d_bsum[blockIdx.x] = sh[1023];
}
__global__ void scan_bsum() {
    if (threadIdx.x == 0) {
        int s = 0;
        for (int b = 0; b < NB; b++) { int v = d_bsum[b]; d_bsum[b] = s; s += v; }
    }
}
__global__ void add_offsets() {
    int i = blockIdx.x * blockDim.x + threadIdx.x;
    if (i < NM) {
        int v = d_rowptr[i] + d_bsum[i >> 10];
        d_rowptr[i] = v;
        d_cursor[i] = v;
    }
    if (i == 0) d_rowptr[NM] = ETOT;
}
// scatter packed payload: src index | rel bit (removes an indirection in agg_out)
__global__ void fill_edges(const int* __restrict__ dst_dm, const int* __restrict__ dst_am,
                           const int* __restrict__ src_dm, const int* __restrict__ src_am) {
    int e = blockIdx.x * blockDim.x + threadIdx.x;
    int d, pay;
    if (e < E0)       { d = dst_dm[e];      pay = src_dm[e]; }
    else if (e < ETOT){ d = dst_am[e - E0]; pay = src_am[e - E0] | 0x80000000; }
    else return;
    int pos = atomicAdd(&d_cursor[d], 1);
    d_epay[pos] = pay;
}

// ---------------- fused: per-edge attention + softmax-agg + gelu + output head ----------------
__device__ __forceinline__ float gelu_exact(float x) { return x * normcdff(x); }

__global__ __launch_bounds__(256)
void agg_out(const float* __restrict__ p_rel, const float* __restrict__ skip,
             const float* __restrict__ blin, float* __restrict__ out) {
    __shared__ float sWc[128 * 8];
    __shared__ float sc[9];   // [0]=g, [1..8]=cvec
    for (int i = threadIdx.x; i < 1024; i += 256) sWc[i] = d_Wcomb[i];
    if (threadIdx.x < 8) {
        float gg = 1.f / (1.f + expf(-skip[0]));
        sc[1 + threadIdx.x] = gg * d_tmp8[threadIdx.x] + blin[threadIdx.x];
        if (threadIdx.x == 0) sc[0] = gg;
    }
    __syncthreads();

    int warp = threadIdx.x >> 5, lane = threadIdx.x & 31;
    int node = blockIdx.x * 8 + warp;        // grid exact: 12500*8 = NM
    int h = lane >> 2;
    const float scale = 0.25f;               // 1/sqrt(16)
    float p0 = p_rel[h] * scale;             // rel 0 (director->movie)
    float p1 = p_rel[8 + h] * scale;         // rel 1 (actor->movie)

    float4 qv = *(const float4*)&d_q0[(size_t)node * 128 + lane * 4];
    int beg = d_rowptr[node], end = d_rowptr[node + 1];

    float4 acc = make_float4(0.f, 0.f, 0.f, 0.f);
    float den = 0.f;
    for (int i = beg; i < end; i++) {
        int pay = d_epay[i];
        int rel = ((unsigned)pay) >> 31;
        int src = pay & 0x7FFFFFFF;
        const float* ktb = rel ? d_ktam : d_ktdm;
        const float* mtb = rel ? d_mtam : d_mtdm;
        float ph = rel ? p1 : p0;
        size_t base = (size_t)src * 128 + lane * 4;
        float4 kt = *(const float4*)(ktb + base);
        float4 mt = *(const float4*)(mtb + base);
        float part = qv.x * kt.x + qv.y * kt.y + qv.z * kt.z + qv.w * kt.w;
        part += __shfl_xor_sync(0xffffffffu, part, 1);
        part += __shfl_xor_sync(0xffffffffu, part, 2);   // head-local dot (4 lanes)
        float a = expf(part * ph);
        den += a;
        acc.x += a * mt.x; acc.y += a * mt.y; acc.z += a * mt.z; acc.w += a * mt.w;
    }
    float inv = (den > 0.f) ? (1.f / den) : 0.f;
    float gl[4];
    gl[0] = gelu_exact(acc.x * inv);
    gl[1] = gelu_exact(acc.y * inv);
    gl[2] = gelu_exact(acc.z * inv);
    gl[3] = gelu_exact(acc.w * inv);

    float o[8] = {0, 0, 0, 0, 0, 0, 0, 0};
    int r0 = lane * 4;
#pragma unroll
    for (int j = 0; j < 4; j++) {
        float gj = gl[j];
        const float* wr = &sWc[(r0 + j) * 8];
#pragma unroll
        for (int c = 0; c < 8; c++) o[c] += gj * wr[c];
    }
#pragma unroll
    for (int off = 16; off > 0; off >>= 1)
#pragma unroll
        for (int c = 0; c < 8; c++) o[c] += __shfl_xor_sync(0xffffffffu, o[c], off);

    if (lane == 0) {
        float g = sc[0];
#pragma unroll
        for (int c = 0; c < 8; c++)
            out[(size_t)node * 8 + c] = g * o[c] + (1.f - g) * d_s0[(size_t)node * 8 + c] + sc[1 + c];
    }
}

// ---------------- launch ----------------
#define SYM(p, s) cudaGetSymbolAddress((void**)&(p), s)

extern "C" void kernel_launch(void* const* d_in, const int* in_sizes, int n_in,
                              void* d_out, int out_size) {
    (void)in_sizes; (void)n_in; (void)out_size;
    const float* x_m   = (const float*)d_in[0];
    const float* x_d   = (const float*)d_in[1];
    const float* x_a   = (const float*)d_in[2];
    const int* src_dm  = (const int*)d_in[3];
    const int* dst_dm  = (const int*)d_in[4];
    const int* src_am  = (const int*)d_in[5];
    const int* dst_am  = (const int*)d_in[6];
    const float* Wpre_m = (const float*)d_in[11];
    const float* Wpre_d = (const float*)d_in[12];
    const float* Wpre_a = (const float*)d_in[13];
    const float* bpre   = (const float*)d_in[14];
    const float* Wk     = (const float*)d_in[15];
    const float* bk     = (const float*)d_in[16];
    const float* Wq     = (const float*)d_in[17];
    const float* bq     = (const float*)d_in[18];
    const float* Wv     = (const float*)d_in[19];
    const float* bv     = (const float*)d_in[20];
    const float* a_rel  = (const float*)d_in[21];
    const float* m_rel  = (const float*)d_in[22];
    const float* p_rel  = (const float*)d_in[23];
    const float* skip   = (const float*)d_in[24];
    const float* Wa     = (const float*)d_in[25];
    const float* ba     = (const float*)d_in[26];
    const float* Wlin   = (const float*)d_in[27];
    const float* blin   = (const float*)d_in[28];
    float* out = (float*)d_out;

    float *WK0, *WV0, *WK1, *WV1, *bK0, *bV0, *bK1, *bV1;
    float *Wqf, *bqf, *Wsf, *bsf;
    float *q0, *s0, *ktdm, *mtdm, *ktam, *mtam;
    int *counts;
    SYM(WK0, d_WK0); SYM(WV0, d_WV0); SYM(WK1, d_WK1); SYM(WV1, d_WV1);
    SYM(bK0, d_bK0); SYM(bV0, d_bV0); SYM(bK1, d_bK1); SYM(bV1, d_bV1);
    SYM(Wqf, d_Wqf); SYM(bqf, d_bqf); SYM(Wsf, d_Wsf); SYM(bsf, d_bsf);
    SYM(q0, d_q0); SYM(s0, d_s0);
    SYM(ktdm, d_ktdm); SYM(mtdm, d_mtdm); SYM(ktam, d_ktam); SYM(mtam, d_mtam);
    SYM(counts, d_counts);

    // 1) fused weight prep (2 launches) + counts clear (memset, capturable)
    cudaMemsetAsync(counts, 0, NM * sizeof(int));
    prep_compose<<<516, 128>>>(Wk, bk, Wv, bv, a_rel, m_rel);
    prep_mm<<<403, 256>>>(Wpre_m, Wpre_d, Wpre_a, bpre, Wq, bq, Wa, ba, Wlin);

    // 2) node-level GEMMs on tensor cores (tf32)
    gemm_tf32<<<782, 256>>>(x_m, Wqf, bqf, q0, NM, 256);   // movie queries
    kernel_s0<<<12500, 256>>>(x_m, Wsf, bsf, s0, NM);      // skip-path xs0@Wlin
    gemm_tf32<<<157, 256>>>(x_d, WK0, bK0, ktdm, ND, 128); // director keys
    gemm_tf32<<<157, 256>>>(x_d, WV0, bV0, mtdm, ND, 128); // director messages
    gemm_tf32<<<391, 256>>>(x_a, WK1, bK1, ktam, NA, 128); // actor keys
    gemm_tf32<<<391, 256>>>(x_a, WV1, bV1, mtam, NA, 128); // actor messages

    // 3) CSR by destination movie node
    count_edges<<<2344, 256>>>(dst_dm, dst_am);
    scan_block<<<NB, 1024>>>();
    scan_bsum<<<1, 32>>>();
    add_offsets<<<391, 256>>>();
    fill_edges<<<2344, 256>>>(dst_dm, dst_am, src_dm, src_am);

    // 4) fused attention + softmax aggregation + gelu + output head
    agg_out<<<12500, 256>>>(p_rel, skip, blin, out);
}

// round 5
// speedup vs baseline: 2.9302x; 1.4057x over previous
#include <cuda_runtime.h>
#include <math.h>
#include <stdint.h>

#define NM 100000
#define ND 20000
#define NA 50000
#define E0 300000
#define ETOT 600000
#define NB 98   // ceil(NM/1024)

// ---------------- scratch (static device memory; no allocs) ----------------
__device__ float d_q0[NM * 128];
__device__ float d_s0[NM * 8];
__device__ float d_ktdm[ND * 128];
__device__ float d_mtdm[ND * 128];
__device__ float d_ktam[NA * 128];
__device__ float d_mtam[NA * 128];
__device__ int   d_counts[NM];
__device__ int   d_cursor[NM];
__device__ int   d_rowptr[NM + 1];
__device__ int   d_bsum[128];
__device__ int   d_epay[ETOT];   // packed: src | (rel<<31)

__device__ float d_WeffK0[128 * 128], d_WeffV0[128 * 128];
__device__ float d_WeffK1[128 * 128], d_WeffV1[128 * 128];
__device__ float d_beffK0[128], d_beffV0[128], d_beffK1[128], d_beffV1[128];
__device__ float d_WK0[128 * 128], d_WV0[128 * 128], d_WK1[128 * 128], d_WV1[128 * 128];
__device__ float d_bK0[128], d_bV0[128], d_bK1[128], d_bV1[128];
__device__ float d_Wqf[256 * 128];
__device__ float d_bqf[128];
__device__ float d_Wsf[256 * 8];
__device__ float d_bsf[8];
__device__ float d_Wcomb[128 * 8];
__device__ float d_tmp8[8];

// ---------------- fused weight-composition kernels ----------------

__global__ void prep_compose(const float* __restrict__ Wk, const float* __restrict__ bk,
                             const float* __restrict__ Wv, const float* __restrict__ bv,
                             const float* __restrict__ a_rel, const float* __restrict__ m_rel) {
    int which = blockIdx.x / 129;
    int i = blockIdx.x - which * 129;
    const float *Win, *bin, *A; float *Weff, *beff;
    switch (which) {
        case 0: Win = Wk + 16384; bin = bk + 128; A = a_rel;        Weff = d_WeffK0; beff = d_beffK0; break;
        case 1: Win = Wk + 32768; bin = bk + 256; A = a_rel + 2048; Weff = d_WeffK1; beff = d_beffK1; break;
        case 2: Win = Wv + 16384; bin = bv + 128; A = m_rel;        Weff = d_WeffV0; beff = d_beffV0; break;
        default:Win = Wv + 32768; bin = bv + 256; A = m_rel + 2048; Weff = d_WeffV1; beff = d_beffV1; break;
    }
    int col = threadIdx.x;
    int h = col >> 4, f = col & 15;
    const float* arow = A + h * 256 + f;
    const float* w = (i < 128) ? (Win + i * 128 + h * 16) : (bin + h * 16);
    float s = 0.f;
#pragma unroll
    for (int d = 0; d < 16; d++) s += w[d] * arow[d * 16];
    if (i < 128) Weff[i * 128 + col] = s;
    else         beff[col] = s;
}

__device__ __forceinline__ void mm_task(const float* __restrict__ A, const float* __restrict__ B,
                                        const float* __restrict__ add, float* __restrict__ C,
                                        int M, int K, int N, int t) {
    if (t >= M * N) return;
    int m = t / N, n = t - m * N;
    float s = add ? add[n] : 0.f;
    for (int k = 0; k < K; k++) s += A[m * K + k] * B[k * N + n];
    C[t] = s;
}

__global__ void prep_mm(const float* __restrict__ Wpre_m, const float* __restrict__ Wpre_d,
                        const float* __restrict__ Wpre_a, const float* __restrict__ bpre,
                        const float* __restrict__ Wq, const float* __restrict__ bq,
                        const float* __restrict__ Wa, const float* __restrict__ ba,
                        const float* __restrict__ Wlin) {
    int b = blockIdx.x;
    int tid = threadIdx.x;
    if (b < 64)        mm_task(Wpre_d, d_WeffK0, nullptr, d_WK0, 128, 128, 128, b * 256 + tid);
    else if (b < 128)  mm_task(Wpre_d, d_WeffV0, nullptr, d_WV0, 128, 128, 128, (b - 64) * 256 + tid);
    else if (b < 192)  mm_task(Wpre_a, d_WeffK1, nullptr, d_WK1, 128, 128, 128, (b - 128) * 256 + tid);
    else if (b < 256)  mm_task(Wpre_a, d_WeffV1, nullptr, d_WV1, 128, 128, 128, (b - 192) * 256 + tid);
    else if (b < 384)  mm_task(Wpre_m, Wq, nullptr, d_Wqf, 256, 128, 128, (b - 256) * 256 + tid);
    else if (b == 384) mm_task(bpre + 128, d_WeffK0, d_beffK0, d_bK0, 1, 128, 128, tid);
    else if (b == 385) mm_task(bpre + 128, d_WeffV0, d_beffV0, d_bV0, 1, 128, 128, tid);
    else if (b == 386) mm_task(bpre + 256, d_WeffK1, d_beffK1, d_bK1, 1, 128, 128, tid);
    else if (b == 387) mm_task(bpre + 256, d_WeffV1, d_beffV1, d_bV1, 1, 128, 128, tid);
    else if (b == 388) mm_task(bpre, Wq, bq, d_bqf, 1, 128, 128, tid);
    else if (b < 397)  mm_task(Wpre_m, Wlin, nullptr, d_Wsf, 256, 128, 8, (b - 389) * 256 + tid);
    else if (b == 397) mm_task(bpre, Wlin, nullptr, d_bsf, 1, 128, 8, tid);
    else if (b < 402)  mm_task(Wa, Wlin, nullptr, d_Wcomb, 128, 128, 8, (b - 398) * 256 + tid);
    else               mm_task(ba, Wlin, nullptr, d_tmp8, 1, 128, 8, tid);
}

// ---------------- pipelined tf32 tensor-core GEMM ----------------
// C[M x 128] = A[M x K] @ W[K x 128] + bias, 2-stage cp.async pipeline.
// Optional fused thin GEMM: S[M x 8] = A[M x 256] @ Wsf + bsf (fp32, from smem A tiles).
// smem layout (floats): As[2][128][36] | Bs[2][32][136] | sWs[2048]

__device__ __forceinline__ void cpa16(void* s, const void* g, int psz) {
    uint32_t sa = (uint32_t)__cvta_generic_to_shared(s);
    asm volatile("cp.async.cg.shared.global [%0], [%1], 16, %2;" :: "r"(sa), "l"(g), "r"(psz));
}

template<int KT, bool FS0>
__device__ __forceinline__ void gemm_body(const float* __restrict__ A, const float* __restrict__ W,
                                          const float* __restrict__ bias, float* __restrict__ C,
                                          int M, int row0,
                                          const float* __restrict__ Wsf, const float* __restrict__ bsf,
                                          float* __restrict__ S) {
    extern __shared__ float smem[];
    float* AsBase = smem;                 // 2 * 128 * 36 = 9216
    float* BsBase = smem + 9216;          // 2 * 32 * 136 = 8704
    float* sWs    = smem + 9216 + 8704;   // 2048

    const int K = KT * 32;
    int tid = threadIdx.x;
    int warp = tid >> 5, lane = tid & 31;
    int wm = warp >> 1, wn = warp & 1;
    int g = lane >> 2, tg = lane & 3;

    if (FS0) {
        for (int i = tid; i < 2048; i += 256) sWs[i] = Wsf[i];
    }

    float acc[2][8][4];
#pragma unroll
    for (int mi = 0; mi < 2; mi++)
#pragma unroll
        for (int ni = 0; ni < 8; ni++)
#pragma unroll
            for (int c = 0; c < 4; c++) acc[mi][ni][c] = 0.f;
    float sacc[4] = {0.f, 0.f, 0.f, 0.f};

    // tile loader
    auto load_tile = [&](int kt, int buf) {
        float* Ab = AsBase + buf * (128 * 36);
        float* Bb = BsBase + buf * (32 * 136);
#pragma unroll
        for (int l = 0; l < 4; l++) {
            int cidx = tid + l * 256;
            int r = cidx >> 3, q = cidx & 7;
            int gr = row0 + r;
            const float* ga = (gr < M) ? &A[(size_t)gr * K + kt * 32 + q * 4] : A;
            cpa16(&Ab[r * 36 + q * 4], ga, (gr < M) ? 16 : 0);
        }
#pragma unroll
        for (int l = 0; l < 4; l++) {
            int cidx = tid + l * 256;
            int k = cidx >> 5, q = cidx & 31;
            cpa16(&Bb[k * 136 + q * 4], &W[(size_t)(kt * 32 + k) * 128 + q * 4], 16);
        }
        asm volatile("cp.async.commit_group;");
    };

    load_tile(0, 0);

    for (int t = 0; t < KT; t++) {
        if (t + 1 < KT) {
            load_tile(t + 1, (t + 1) & 1);
            asm volatile("cp.async.wait_group 1;");
        } else {
            asm volatile("cp.async.wait_group 0;");
        }
        __syncthreads();

        float* Ab = AsBase + (t & 1) * (128 * 36);
        float* Bb = BsBase + (t & 1) * (32 * 136);

#pragma unroll
        for (int ks = 0; ks < 32; ks += 8) {
            uint32_t a_[2][4];
#pragma unroll
            for (int mi = 0; mi < 2; mi++) {
                int ar = wm * 32 + mi * 16 + g;
                a_[mi][0] = __float_as_uint(Ab[ar * 36 + ks + tg]);
                a_[mi][1] = __float_as_uint(Ab[(ar + 8) * 36 + ks + tg]);
                a_[mi][2] = __float_as_uint(Ab[ar * 36 + ks + tg + 4]);
                a_[mi][3] = __float_as_uint(Ab[(ar + 8) * 36 + ks + tg + 4]);
            }
#pragma unroll
            for (int ni = 0; ni < 8; ni++) {
                int bc = wn * 64 + ni * 8 + g;
                uint32_t b0 = __float_as_uint(Bb[(ks + tg) * 136 + bc]);
                uint32_t b1 = __float_as_uint(Bb[(ks + tg + 4) * 136 + bc]);
#pragma unroll
                for (int mi = 0; mi < 2; mi++) {
                    asm volatile(
                        "mma.sync.aligned.m16n8k8.row.col.f32.tf32.tf32.f32 "
                        "{%0,%1,%2,%3}, {%4,%5,%6,%7}, {%8,%9}, {%0,%1,%2,%3};"
                        : "+f"(acc[mi][ni][0]), "+f"(acc[mi][ni][1]),
                          "+f"(acc[mi][ni][2]), "+f"(acc[mi][ni][3])
                        : "r"(a_[mi][0]), "r"(a_[mi][1]), "r"(a_[mi][2]), "r"(a_[mi][3]),
                          "r"(b0), "r"(b1));
                }
            }
        }

        if (FS0) {
            int r = tid >> 1, cg4 = (tid & 1) * 4;
            const float* Ar = &Ab[r * 36];
            const float* Wr = &sWs[t * 32 * 8 + cg4];
#pragma unroll
            for (int kk = 0; kk < 32; kk++) {
                float av = Ar[kk];
                float4 w = *(const float4*)&Wr[kk * 8];
                sacc[0] += av * w.x; sacc[1] += av * w.y;
                sacc[2] += av * w.z; sacc[3] += av * w.w;
            }
        }
        __syncthreads();
    }

#pragma unroll
    for (int mi = 0; mi < 2; mi++) {
#pragma unroll
        for (int ni = 0; ni < 8; ni++) {
            int col = wn * 64 + ni * 8 + tg * 2;
            float bx = bias[col], by = bias[col + 1];
            int r1 = row0 + wm * 32 + mi * 16 + g;
            if (r1 < M) {
                float2 o = make_float2(acc[mi][ni][0] + bx, acc[mi][ni][1] + by);
                *(float2*)&C[(size_t)r1 * 128 + col] = o;
            }
            int r2 = r1 + 8;
            if (r2 < M) {
                float2 o = make_float2(acc[mi][ni][2] + bx, acc[mi][ni][3] + by);
                *(float2*)&C[(size_t)r2 * 128 + col] = o;
            }
        }
    }

    if (FS0) {
        int r = tid >> 1, cg4 = (tid & 1) * 4;
        int gr = row0 + r;
        if (gr < M) {
            float4 o;
            o.x = sacc[0] + bsf[cg4 + 0];
            o.y = sacc[1] + bsf[cg4 + 1];
            o.z = sacc[2] + bsf[cg4 + 2];
            o.w = sacc[3] + bsf[cg4 + 3];
            *(float4*)&S[(size_t)gr * 8 + cg4] = o;
        }
    }
}

// q0 GEMM (K=256) with fused s0 thin GEMM
__global__ __launch_bounds__(256, 2)
void gemm_q0(const float* __restrict__ A) {
    gemm_body<8, true>(A, d_Wqf, d_bqf, d_q0, NM, blockIdx.x * 128, d_Wsf, d_bsf, d_s0);
}

// merged K/V GEMMs (K=128): 1096 blocks = 157+157+391+391
__global__ __launch_bounds__(256, 2)
void gemm_kv(const float* __restrict__ x_d, const float* __restrict__ x_a) {
    int b = blockIdx.x;
    if (b < 157)      gemm_body<4, false>(x_d, d_WK0, d_bK0, d_ktdm, ND, b * 128, nullptr, nullptr, nullptr);
    else if (b < 314) gemm_body<4, false>(x_d, d_WV0, d_bV0, d_mtdm, ND, (b - 157) * 128, nullptr, nullptr, nullptr);
    else if (b < 705) gemm_body<4, false>(x_a, d_WK1, d_bK1, d_ktam, NA, (b - 314) * 128, nullptr, nullptr, nullptr);
    else              gemm_body<4, false>(x_a, d_WV1, d_bV1, d_mtam, NA, (b - 705) * 128, nullptr, nullptr, nullptr);
}

// ---------------- CSR build (counting sort by destination movie node) ----------------
__global__ void count_edges(const int* __restrict__ dst_dm, const int* __restrict__ dst_am) {
    int e = blockIdx.x * blockDim.x + threadIdx.x;
    if (e < E0) atomicAdd(&d_counts[dst_dm[e]], 1);
    else if (e < ETOT) atomicAdd(&d_counts[dst_am[e - E0]], 1);
}
__global__ void scan_block() {
    __shared__ int sh[1024];
    int i = blockIdx.x * 1024 + threadIdx.x;
    int v = (i < NM) ? d_counts[i] : 0;
    sh[threadIdx.x] = v;
    __syncthreads();
    for (int off = 1; off < 1024; off <<= 1) {
        int t = (threadIdx.x >= off) ? sh[threadIdx.x - off] : 0;
        __syncthreads();
        sh[threadIdx.x] += t;
        __syncthreads();
    }
    if (i < NM) d_rowptr[i] = sh[threadIdx.x] - v;
    if (threadIdx.x == 1023) d_bsum[blockIdx.x] = sh[1023];
}
__global__ void scan_bsum() {
    if (threadIdx.x == 0) {
        int s = 0;
        for (int b = 0; b < NB; b++) { int v = d_bsum[b]; d_bsum[b] = s; s += v; }
    }
}
__global__ void add_offsets() {
    int i = blockIdx.x * blockDim.x + threadIdx.x;
    if (i < NM) {
        int v = d_rowptr[i] + d_bsum[i >> 10];
        d_rowptr[i] = v;
        d_cursor[i] = v;
    }
    if (i == 0) d_rowptr[NM] = ETOT;
}
__global__ void fill_edges(const int* __restrict__ dst_dm, const int* __restrict__ dst_am,
                           const int* __restrict__ src_dm, const int* __restrict__ src_am) {
    int e = blockIdx.x * blockDim.x + threadIdx.x;
    int d, pay;
    if (e < E0)       { d = dst_dm[e];      pay = src_dm[e]; }
    else if (e < ETOT){ d = dst_am[e - E0]; pay = src_am[e - E0] | 0x80000000; }
    else return;
    int pos = atomicAdd(&d_cursor[d], 1);
    d_epay[pos] = pay;
}

// ---------------- fused: per-edge attention + softmax-agg + gelu + output head ----------------
__device__ __forceinline__ float gelu_exact(float x) { return x * normcdff(x); }

__global__ __launch_bounds__(256)
void agg_out(const float* __restrict__ p_rel, const float* __restrict__ skip,
             const float* __restrict__ blin, float* __restrict__ out) {
    __shared__ float sWc[128 * 8];
    __shared__ float sc[9];
    for (int i = threadIdx.x; i < 1024; i += 256) sWc[i] = d_Wcomb[i];
    if (threadIdx.x < 8) {
        float gg = 1.f / (1.f + expf(-skip[0]));
        sc[1 + threadIdx.x] = gg * d_tmp8[threadIdx.x] + blin[threadIdx.x];
        if (threadIdx.x == 0) sc[0] = gg;
    }
    __syncthreads();

    int warp = threadIdx.x >> 5, lane = threadIdx.x & 31;
    int node = blockIdx.x * 8 + warp;
    int h = lane >> 2;
    const float scale = 0.25f;
    float p0 = p_rel[h] * scale;
    float p1 = p_rel[8 + h] * scale;

    float4 qv = *(const float4*)&d_q0[(size_t)node * 128 + lane * 4];
    int beg = d_rowptr[node], end = d_rowptr[node + 1];

    float4 acc = make_float4(0.f, 0.f, 0.f, 0.f);
    float den = 0.f;
    int i = beg;
    // unroll-2: issue both payloads then all 4 vector loads before consuming
    for (; i + 2 <= end; i += 2) {
        int pay0 = d_epay[i], pay1 = d_epay[i + 1];
        unsigned u0 = (unsigned)pay0, u1 = (unsigned)pay1;
        int src0 = pay0 & 0x7FFFFFFF, src1 = pay1 & 0x7FFFFFFF;
        const float* kb0 = (u0 >> 31) ? d_ktam : d_ktdm;
        const float* mb0 = (u0 >> 31) ? d_mtam : d_mtdm;
        const float* kb1 = (u1 >> 31) ? d_ktam : d_ktdm;
        const float* mb1 = (u1 >> 31) ? d_mtam : d_mtdm;
        float ph0 = (u0 >> 31) ? p1 : p0;
        float ph1 = (u1 >> 31) ? p1 : p0;
        size_t b0 = (size_t)src0 * 128 + lane * 4;
        size_t b1 = (size_t)src1 * 128 + lane * 4;
        float4 k0 = *(const float4*)(kb0 + b0);
        float4 m0 = *(const float4*)(mb0 + b0);
        float4 k1 = *(const float4*)(kb1 + b1);
        float4 m1 = *(const float4*)(mb1 + b1);
        float d0 = qv.x * k0.x + qv.y * k0.y + qv.z * k0.z + qv.w * k0.w;
        float d1 = qv.x * k1.x + qv.y * k1.y + qv.z * k1.z + qv.w * k1.w;
        d0 += __shfl_xor_sync(0xffffffffu, d0, 1);
        d1 += __shfl_xor_sync(0xffffffffu, d1, 1);
        d0 += __shfl_xor_sync(0xffffffffu, d0, 2);
        d1 += __shfl_xor_sync(0xffffffffu, d1, 2);
        float a0 = __expf(d0 * ph0);
        float a1 = __expf(d1 * ph1);
        den += a0 + a1;
        acc.x += a0 * m0.x + a1 * m1.x;
        acc.y += a0 * m0.y + a1 * m1.y;
        acc.z += a0 * m0.z + a1 * m1.z;
        acc.w += a0 * m0.w + a1 * m1.w;
    }
    if (i < end) {
        int pay = d_epay[i];
        unsigned u = (unsigned)pay;
        int src = pay & 0x7FFFFFFF;
        const float* kb = (u >> 31) ? d_ktam : d_ktdm;
        const float* mb = (u >> 31) ? d_mtam : d_mtdm;
        float ph = (u >> 31) ? p1 : p0;
        size_t b = (size_t)src * 128 + lane * 4;
        float4 k0 = *(const float4*)(kb + b);
        float4 m0 = *(const float4*)(mb + b);
        float d0 = qv.x * k0.x + qv.y * k0.y + qv.z * k0.z + qv.w * k0.w;
        d0 += __shfl_xor_sync(0xffffffffu, d0, 1);
        d0 += __shfl_xor_sync(0xffffffffu, d0, 2);
        float a0 = __expf(d0 * ph);
        den += a0;
        acc.x += a0 * m0.x; acc.y += a0 * m0.y;
        acc.z += a0 * m0.z; acc.w += a0 * m0.w;
    }

    float inv = (den > 0.f) ? (1.f / den) : 0.f;
    float gl[4];
    gl[0] = gelu_exact(acc.x * inv);
    gl[1] = gelu_exact(acc.y * inv);
    gl[2] = gelu_exact(acc.z * inv);
    gl[3] = gelu_exact(acc.w * inv);

    float o[8] = {0, 0, 0, 0, 0, 0, 0, 0};
    int r0 = lane * 4;
#pragma unroll
    for (int j = 0; j < 4; j++) {
        float gj = gl[j];
        const float* wr = &sWc[(r0 + j) * 8];
#pragma unroll
        for (int c = 0; c < 8; c++) o[c] += gj * wr[c];
    }
#pragma unroll
    for (int off = 16; off > 0; off >>= 1)
#pragma unroll
        for (int c = 0; c < 8; c++) o[c] += __shfl_xor_sync(0xffffffffu, o[c], off);

    if (lane == 0) {
        float g = sc[0];
        const float* s0p = &d_s0[(size_t)node * 8];
        float4 o1, o2;
        o1.x = g * o[0] + (1.f - g) * s0p[0] + sc[1];
        o1.y = g * o[1] + (1.f - g) * s0p[1] + sc[2];
        o1.z = g * o[2] + (1.f - g) * s0p[2] + sc[3];
        o1.w = g * o[3] + (1.f - g) * s0p[3] + sc[4];
        o2.x = g * o[4] + (1.f - g) * s0p[4] + sc[5];
        o2.y = g * o[5] + (1.f - g) * s0p[5] + sc[6];
        o2.z = g * o[6] + (1.f - g) * s0p[6] + sc[7];
        o2.w = g * o[7] + (1.f - g) * s0p[7] + sc[8];
        *(float4*)&out[(size_t)node * 8] = o1;
        *(float4*)&out[(size_t)node * 8 + 4] = o2;
    }
}

// ---------------- launch ----------------
#define SYM(p, s) cudaGetSymbolAddress((void**)&(p), s)

extern "C" void kernel_launch(void* const* d_in, const int* in_sizes, int n_in,
                              void* d_out, int out_size) {
    (void)in_sizes; (void)n_in; (void)out_size;
    const float* x_m   = (const float*)d_in[0];
    const float* x_d   = (const float*)d_in[1];
    const float* x_a   = (const float*)d_in[2];
    const int* src_dm  = (const int*)d_in[3];
    const int* dst_dm  = (const int*)d_in[4];
    const int* src_am  = (const int*)d_in[5];
    const int* dst_am  = (const int*)d_in[6];
    const float* Wpre_m = (const float*)d_in[11];
    const float* Wpre_d = (const float*)d_in[12];
    const float* Wpre_a = (const float*)d_in[13];
    const float* bpre   = (const float*)d_in[14];
    const float* Wk     = (const float*)d_in[15];
    const float* bk     = (const float*)d_in[16];
    const float* Wq     = (const float*)d_in[17];
    const float* bq     = (const float*)d_in[18];
    const float* Wv     = (const float*)d_in[19];
    const float* bv     = (const float*)d_in[20];
    const float* a_rel  = (const float*)d_in[21];
    const float* m_rel  = (const float*)d_in[22];
    const float* p_rel  = (const float*)d_in[23];
    const float* skip   = (const float*)d_in[24];
    const float* Wa     = (const float*)d_in[25];
    const float* ba     = (const float*)d_in[26];
    const float* Wlin   = (const float*)d_in[27];
    const float* blin   = (const float*)d_in[28];
    float* out = (float*)d_out;

    int* counts;
    SYM(counts, d_counts);

    // dynamic smem sizes for the pipelined GEMMs
    const int SMEM_Q0 = (9216 + 8704 + 2048) * 4;   // 79872 B
    const int SMEM_KV = (9216 + 8704 + 2048) * 4;   // same layout
    static int attr_set = 0;
    if (!attr_set) {
        cudaFuncSetAttribute(gemm_q0, cudaFuncAttributeMaxDynamicSharedMemorySize, SMEM_Q0);
        cudaFuncSetAttribute(gemm_kv, cudaFuncAttributeMaxDynamicSharedMemorySize, SMEM_KV);
        attr_set = 1;
    }

    // 1) weight prep + counts clear
    cudaMemsetAsync(counts, 0, NM * sizeof(int));
    prep_compose<<<516, 128>>>(Wk, bk, Wv, bv, a_rel, m_rel);
    prep_mm<<<403, 256>>>(Wpre_m, Wpre_d, Wpre_a, bpre, Wq, bq, Wa, ba, Wlin);

    // 2) CSR by destination movie node (before GEMMs so GEMM outputs stay hot in L2)
    count_edges<<<2344, 256>>>(dst_dm, dst_am);
    scan_block<<<NB, 1024>>>();
    scan_bsum<<<1, 32>>>();
    add_offsets<<<391, 256>>>();
    fill_edges<<<2344, 256>>>(dst_dm, dst_am, src_dm, src_am);

    // 3) node-level GEMMs (tf32 tensor cores, cp.async 2-stage pipeline)
    gemm_q0<<<782, 256, SMEM_Q0>>>(x_m);        // movie queries + fused skip-path s0
    gemm_kv<<<1096, 256, SMEM_KV>>>(x_d, x_a);  // all 4 key/message GEMMs merged

    // 4) fused attention + softmax aggregation + gelu + output head
    agg_out<<<12500, 256>>>(p_rel, skip, blin, out);
}

// round 6
// speedup vs baseline: 3.1420x; 1.0723x over previous
#include <cuda_runtime.h>
#include <cuda_fp16.h>
#include <math.h>
#include <stdint.h>

#define NM 100000
#define ND 20000
#define NA 50000
#define E0 300000
#define ETOT 600000
#define NB 98   // ceil(NM/1024)

// ---------------- scratch (static device memory; no allocs) ----------------
__device__ float  d_q0[NM * 128];
__device__ float  d_s0[NM * 8];
__device__ __half d_ktdm[ND * 128];
__device__ __half d_mtdm[ND * 128];
__device__ __half d_ktam[NA * 128];
__device__ __half d_mtam[NA * 128];
__device__ int    d_counts[NM];
__device__ int    d_cursor[NM];
__device__ int    d_rowptr[NM + 1];
__device__ int    d_bsum[128];
__device__ int    d_epay[ETOT];   // packed: src | (rel<<31)

__device__ float d_WeffK0[128 * 128], d_WeffV0[128 * 128];
__device__ float d_WeffK1[128 * 128], d_WeffV1[128 * 128];
__device__ float d_beffK0[128], d_beffV0[128], d_beffK1[128], d_beffV1[128];
__device__ float d_WK0[128 * 128], d_WV0[128 * 128], d_WK1[128 * 128], d_WV1[128 * 128];
__device__ float d_bK0[128], d_bV0[128], d_bK1[128], d_bV1[128];
__device__ float d_Wqf[256 * 128];
__device__ float d_bqf[128];
__device__ float d_Wsf[256 * 8];
__device__ float d_bsf[8];
__device__ float d_Wcomb[128 * 8];
__device__ float d_tmp8[8];

// ---------------- fused weight-composition kernels ----------------

__global__ void prep_compose(const float* __restrict__ Wk, const float* __restrict__ bk,
                             const float* __restrict__ Wv, const float* __restrict__ bv,
                             const float* __restrict__ a_rel, const float* __restrict__ m_rel) {
    int which = blockIdx.x / 129;
    int i = blockIdx.x - which * 129;
    const float *Win, *bin, *A; float *Weff, *beff;
    switch (which) {
        case 0: Win = Wk + 16384; bin = bk + 128; A = a_rel;        Weff = d_WeffK0; beff = d_beffK0; break;
        case 1: Win = Wk + 32768; bin = bk + 256; A = a_rel + 2048; Weff = d_WeffK1; beff = d_beffK1; break;
        case 2: Win = Wv + 16384; bin = bv + 128; A = m_rel;        Weff = d_WeffV0; beff = d_beffV0; break;
        default:Win = Wv + 32768; bin = bv + 256; A = m_rel + 2048; Weff = d_WeffV1; beff = d_beffV1; break;
    }
    int col = threadIdx.x;
    int h = col >> 4, f = col & 15;
    const float* arow = A + h * 256 + f;
    const float* w = (i < 128) ? (Win + i * 128 + h * 16) : (bin + h * 16);
    float s = 0.f;
#pragma unroll
    for (int d = 0; d < 16; d++) s += w[d] * arow[d * 16];
    if (i < 128) Weff[i * 128 + col] = s;
    else         beff[col] = s;
}

__device__ __forceinline__ void mm_task(const float* __restrict__ A, const float* __restrict__ B,
                                        const float* __restrict__ add, float* __restrict__ C,
                                        int M, int K, int N, int t) {
    if (t >= M * N) return;
    int m = t / N, n = t - m * N;
    float s = add ? add[n] : 0.f;
    for (int k = 0; k < K; k++) s += A[m * K + k] * B[k * N + n];
    C[t] = s;
}

__global__ void prep_mm(const float* __restrict__ Wpre_m, const float* __restrict__ Wpre_d,
                        const float* __restrict__ Wpre_a, const float* __restrict__ bpre,
                        const float* __restrict__ Wq, const float* __restrict__ bq,
                        const float* __restrict__ Wa, const float* __restrict__ ba,
                        const float* __restrict__ Wlin) {
    int b = blockIdx.x;
    int tid = threadIdx.x;
    if (b < 64)        mm_task(Wpre_d, d_WeffK0, nullptr, d_WK0, 128, 128, 128, b * 256 + tid);
    else if (b < 128)  mm_task(Wpre_d, d_WeffV0, nullptr, d_WV0, 128, 128, 128, (b - 64) * 256 + tid);
    else if (b < 192)  mm_task(Wpre_a, d_WeffK1, nullptr, d_WK1, 128, 128, 128, (b - 128) * 256 + tid);
    else if (b < 256)  mm_task(Wpre_a, d_WeffV1, nullptr, d_WV1, 128, 128, 128, (b - 192) * 256 + tid);
    else if (b < 384)  mm_task(Wpre_m, Wq, nullptr, d_Wqf, 256, 128, 128, (b - 256) * 256 + tid);
    else if (b == 384) mm_task(bpre + 128, d_WeffK0, d_beffK0, d_bK0, 1, 128, 128, tid);
    else if (b == 385) mm_task(bpre + 128, d_WeffV0, d_beffV0, d_bV0, 1, 128, 128, tid);
    else if (b == 386) mm_task(bpre + 256, d_WeffK1, d_beffK1, d_bK1, 1, 128, 128, tid);
    else if (b == 387) mm_task(bpre + 256, d_WeffV1, d_beffV1, d_bV1, 1, 128, 128, tid);
    else if (b == 388) mm_task(bpre, Wq, bq, d_bqf, 1, 128, 128, tid);
    else if (b < 397)  mm_task(Wpre_m, Wlin, nullptr, d_Wsf, 256, 128, 8, (b - 389) * 256 + tid);
    else if (b == 397) mm_task(bpre, Wlin, nullptr, d_bsf, 1, 128, 8, tid);
    else if (b < 402)  mm_task(Wa, Wlin, nullptr, d_Wcomb, 128, 128, 8, (b - 398) * 256 + tid);
    else               mm_task(ba, Wlin, nullptr, d_tmp8, 1, 128, 8, tid);
}

// ---------------- pipelined tf32 tensor-core GEMM ----------------
// C[M x 128] = A[M x K] @ W[K x 128] + bias, 2-stage cp.async pipeline.
// HOUT: write __half output. FS0: fused thin GEMM S = A @ Wsf + bsf (fp32 from smem A).
// smem layout (floats): As[2][128][36] | Bs[2][32][136] | sWs[2048]

__device__ __forceinline__ void cpa16(void* s, const void* g, int psz) {
    uint32_t sa = (uint32_t)__cvta_generic_to_shared(s);
    asm volatile("cp.async.cg.shared.global [%0], [%1], 16, %2;" :: "r"(sa), "l"(g), "r"(psz));
}

template<int KT, bool FS0, bool HOUT>
__device__ __forceinline__ void gemm_body(const float* __restrict__ A, const float* __restrict__ W,
                                          const float* __restrict__ bias, void* __restrict__ Cv,
                                          int M, int row0,
                                          const float* __restrict__ Wsf, const float* __restrict__ bsf,
                                          float* __restrict__ S) {
    extern __shared__ float smem[];
    float* AsBase = smem;                 // 2 * 128 * 36 = 9216
    float* BsBase = smem + 9216;          // 2 * 32 * 136 = 8704
    float* sWs    = smem + 9216 + 8704;   // 2048

    const int K = KT * 32;
    int tid = threadIdx.x;
    int warp = tid >> 5, lane = tid & 31;
    int wm = warp >> 1, wn = warp & 1;
    int g = lane >> 2, tg = lane & 3;

    if (FS0) {
        for (int i = tid; i < 2048; i += 256) sWs[i] = Wsf[i];
    }

    float acc[2][8][4];
#pragma unroll
    for (int mi = 0; mi < 2; mi++)
#pragma unroll
        for (int ni = 0; ni < 8; ni++)
#pragma unroll
            for (int c = 0; c < 4; c++) acc[mi][ni][c] = 0.f;
    float sacc[4] = {0.f, 0.f, 0.f, 0.f};

    auto load_tile = [&](int kt, int buf) {
        float* Ab = AsBase + buf * (128 * 36);
        float* Bb = BsBase + buf * (32 * 136);
#pragma unroll
        for (int l = 0; l < 4; l++) {
            int cidx = tid + l * 256;
            int r = cidx >> 3, q = cidx & 7;
            int gr = row0 + r;
            const float* ga = (gr < M) ? &A[(size_t)gr * K + kt * 32 + q * 4] : A;
            cpa16(&Ab[r * 36 + q * 4], ga, (gr < M) ? 16 : 0);
        }
#pragma unroll
        for (int l = 0; l < 4; l++) {
            int cidx = tid + l * 256;
            int k = cidx >> 5, q = cidx & 31;
            cpa16(&Bb[k * 136 + q * 4], &W[(size_t)(kt * 32 + k) * 128 + q * 4], 16);
        }
        asm volatile("cp.async.commit_group;");
    };

    load_tile(0, 0);

    for (int t = 0; t < KT; t++) {
        if (t + 1 < KT) {
            load_tile(t + 1, (t + 1) & 1);
            asm volatile("cp.async.wait_group 1;");
        } else {
            asm volatile("cp.async.wait_group 0;");
        }
        __syncthreads();

        float* Ab = AsBase + (t & 1) * (128 * 36);
        float* Bb = BsBase + (t & 1) * (32 * 136);

#pragma unroll
        for (int ks = 0; ks < 32; ks += 8) {
            uint32_t a_[2][4];
#pragma unroll
            for (int mi = 0; mi < 2; mi++) {
                int ar = wm * 32 + mi * 16 + g;
                a_[mi][0] = __float_as_uint(Ab[ar * 36 + ks + tg]);
                a_[mi][1] = __float_as_uint(Ab[(ar + 8) * 36 + ks + tg]);
                a_[mi][2] = __float_as_uint(Ab[ar * 36 + ks + tg + 4]);
                a_[mi][3] = __float_as_uint(Ab[(ar + 8) * 36 + ks + tg + 4]);
            }
#pragma unroll
            for (int ni = 0; ni < 8; ni++) {
                int bc = wn * 64 + ni * 8 + g;
                uint32_t b0 = __float_as_uint(Bb[(ks + tg) * 136 + bc]);
                uint32_t b1 = __float_as_uint(Bb[(ks + tg + 4) * 136 + bc]);
#pragma unroll
                for (int mi = 0; mi < 2; mi++) {
                    asm volatile(
                        "mma.sync.aligned.m16n8k8.row.col.f32.tf32.tf32.f32 "
                        "{%0,%1,%2,%3}, {%4,%5,%6,%7}, {%8,%9}, {%0,%1,%2,%3};"
                        : "+f"(acc[mi][ni][0]), "+f"(acc[mi][ni][1]),
                          "+f"(acc[mi][ni][2]), "+f"(acc[mi][ni][3])
                        : "r"(a_[mi][0]), "r"(a_[mi][1]), "r"(a_[mi][2]), "r"(a_[mi][3]),
                          "r"(b0), "r"(b1));
                }
            }
        }

        if (FS0) {
            int r = tid >> 1, cg4 = (tid & 1) * 4;
            const float* Ar = &Ab[r * 36];
            const float* Wr = &sWs[t * 32 * 8 + cg4];
#pragma unroll
            for (int kk = 0; kk < 32; kk++) {
                float av = Ar[kk];
                float4 w = *(const float4*)&Wr[kk * 8];
                sacc[0] += av * w.x; sacc[1] += av * w.y;
                sacc[2] += av * w.z; sacc[3] += av * w.w;
            }
        }
        __syncthreads();
    }

#pragma unroll
    for (int mi = 0; mi < 2; mi++) {
#pragma unroll
        for (int ni = 0; ni < 8; ni++) {
            int col = wn * 64 + ni * 8 + tg * 2;
            float bx = bias[col], by = bias[col + 1];
            int r1 = row0 + wm * 32 + mi * 16 + g;
            int r2 = r1 + 8;
            if (HOUT) {
                __half* C = (__half*)Cv;
                if (r1 < M)
                    *(__half2*)&C[(size_t)r1 * 128 + col] =
                        __floats2half2_rn(acc[mi][ni][0] + bx, acc[mi][ni][1] + by);
                if (r2 < M)
                    *(__half2*)&C[(size_t)r2 * 128 + col] =
                        __floats2half2_rn(acc[mi][ni][2] + bx, acc[mi][ni][3] + by);
            } else {
                float* C = (float*)Cv;
                if (r1 < M) {
                    float2 o = make_float2(acc[mi][ni][0] + bx, acc[mi][ni][1] + by);
                    *(float2*)&C[(size_t)r1 * 128 + col] = o;
                }
                if (r2 < M) {
                    float2 o = make_float2(acc[mi][ni][2] + bx, acc[mi][ni][3] + by);
                    *(float2*)&C[(size_t)r2 * 128 + col] = o;
                }
            }
        }
    }

    if (FS0) {
        int r = tid >> 1, cg4 = (tid & 1) * 4;
        int gr = row0 + r;
        if (gr < M) {
            float4 o;
            o.x = sacc[0] + bsf[cg4 + 0];
            o.y = sacc[1] + bsf[cg4 + 1];
            o.z = sacc[2] + bsf[cg4 + 2];
            o.w = sacc[3] + bsf[cg4 + 3];
            *(float4*)&S[(size_t)gr * 8 + cg4] = o;
        }
    }
}

// single merged GEMM launch: q0 (782 blocks, K=256, fused s0) + 4 K/V GEMMs (1096 blocks, K=128)
__global__ __launch_bounds__(256, 2)
void gemm_all(const float* __restrict__ x_m, const float* __restrict__ x_d,
              const float* __restrict__ x_a) {
    int b = blockIdx.x;
    if (b < 782) {
        gemm_body<8, true, false>(x_m, d_Wqf, d_bqf, d_q0, NM, b * 128, d_Wsf, d_bsf, d_s0);
        return;
    }
    b -= 782;
    if (b < 157)      gemm_body<4, false, true>(x_d, d_WK0, d_bK0, d_ktdm, ND, b * 128, nullptr, nullptr, nullptr);
    else if (b < 314) gemm_body<4, false, true>(x_d, d_WV0, d_bV0, d_mtdm, ND, (b - 157) * 128, nullptr, nullptr, nullptr);
    else if (b < 705) gemm_body<4, false, true>(x_a, d_WK1, d_bK1, d_ktam, NA, (b - 314) * 128, nullptr, nullptr, nullptr);
    else              gemm_body<4, false, true>(x_a, d_WV1, d_bV1, d_mtam, NA, (b - 705) * 128, nullptr, nullptr, nullptr);
}

// ---------------- CSR build (counting sort by destination movie node) ----------------
__global__ void count_edges(const int* __restrict__ dst_dm, const int* __restrict__ dst_am) {
    int e = blockIdx.x * blockDim.x + threadIdx.x;
    if (e < E0) atomicAdd(&d_counts[dst_dm[e]], 1);
    else if (e < ETOT) atomicAdd(&d_counts[dst_am[e - E0]], 1);
}
__global__ void scan_block() {
    __shared__ int sh[1024];
    int i = blockIdx.x * 1024 + threadIdx.x;
    int v = (i < NM) ? d_counts[i] : 0;
    sh[threadIdx.x] = v;
    __syncthreads();
    for (int off = 1; off < 1024; off <<= 1) {
        int t = (threadIdx.x >= off) ? sh[threadIdx.x - off] : 0;
        __syncthreads();
        sh[threadIdx.x] += t;
        __syncthreads();
    }
    if (i < NM) d_rowptr[i] = sh[threadIdx.x] - v;
    if (threadIdx.x == 1023) d_bsum[blockIdx.x] = sh[1023];
}
__global__ void scan_bsum() {
    if (threadIdx.x == 0) {
        int s = 0;
        for (int b = 0; b < NB; b++) { int v = d_bsum[b]; d_bsum[b] = s; s += v; }
    }
}
__global__ void add_offsets() {
    int i = blockIdx.x * blockDim.x + threadIdx.x;
    if (i < NM) {
        int v = d_rowptr[i] + d_bsum[i >> 10];
        d_rowptr[i] = v;
        d_cursor[i] = v;
    }
    if (i == 0) d_rowptr[NM] = ETOT;
}
__global__ void fill_edges(const int* __restrict__ dst_dm, const int* __restrict__ dst_am,
                           const int* __restrict__ src_dm, const int* __restrict__ src_am) {
    int e = blockIdx.x * blockDim.x + threadIdx.x;
    int d, pay;
    if (e < E0)       { d = dst_dm[e];      pay = src_dm[e]; }
    else if (e < ETOT){ d = dst_am[e - E0]; pay = src_am[e - E0] | 0x80000000; }
    else return;
    int pos = atomicAdd(&d_cursor[d], 1);
    d_epay[pos] = pay;
}

// ---------------- fused: per-edge attention + softmax-agg + gelu + output head ----------------
__device__ __forceinline__ float gelu_exact(float x) { return x * normcdff(x); }

__device__ __forceinline__ void half8_dot_acc(const __half* base, size_t off,
                                              float4& out4) {
    uint2 w = *(const uint2*)(base + off);
    float2 lo = __half22float2(*(__half2*)&w.x);
    float2 hi = __half22float2(*(__half2*)&w.y);
    out4.x = lo.x; out4.y = lo.y; out4.z = hi.x; out4.w = hi.y;
}

__global__ __launch_bounds__(256)
void agg_out(const float* __restrict__ p_rel, const float* __restrict__ skip,
             const float* __restrict__ blin, float* __restrict__ out) {
    __shared__ float sWc[128 * 8];
    __shared__ float sc[9];
    for (int i = threadIdx.x; i < 1024; i += 256) sWc[i] = d_Wcomb[i];
    if (threadIdx.x < 8) {
        float gg = 1.f / (1.f + expf(-skip[0]));
        sc[1 + threadIdx.x] = gg * d_tmp8[threadIdx.x] + blin[threadIdx.x];
        if (threadIdx.x == 0) sc[0] = gg;
    }
    __syncthreads();

    int warp = threadIdx.x >> 5, lane = threadIdx.x & 31;
    int node = blockIdx.x * 8 + warp;
    int h = lane >> 2;
    const float scale = 0.25f;
    float p0 = p_rel[h] * scale;
    float p1 = p_rel[8 + h] * scale;

    float4 qv = *(const float4*)&d_q0[(size_t)node * 128 + lane * 4];
    int beg = d_rowptr[node], end = d_rowptr[node + 1];

    float4 acc = make_float4(0.f, 0.f, 0.f, 0.f);
    float den = 0.f;
    int i = beg;
    for (; i + 2 <= end; i += 2) {
        int pay0 = d_epay[i], pay1 = d_epay[i + 1];
        unsigned u0 = (unsigned)pay0, u1 = (unsigned)pay1;
        int src0 = pay0 & 0x7FFFFFFF, src1 = pay1 & 0x7FFFFFFF;
        const __half* kb0 = (u0 >> 31) ? d_ktam : d_ktdm;
        const __half* mb0 = (u0 >> 31) ? d_mtam : d_mtdm;
        const __half* kb1 = (u1 >> 31) ? d_ktam : d_ktdm;
        const __half* mb1 = (u1 >> 31) ? d_mtam : d_mtdm;
        float ph0 = (u0 >> 31) ? p1 : p0;
        float ph1 = (u1 >> 31) ? p1 : p0;
        size_t b0 = (size_t)src0 * 128 + lane * 4;
        size_t b1 = (size_t)src1 * 128 + lane * 4;
        float4 k0, m0, k1, m1;
        half8_dot_acc(kb0, b0, k0);
        half8_dot_acc(mb0, b0, m0);
        half8_dot_acc(kb1, b1, k1);
        half8_dot_acc(mb1, b1, m1);
        float d0 = qv.x * k0.x + qv.y * k0.y + qv.z * k0.z + qv.w * k0.w;
        float d1 = qv.x * k1.x + qv.y * k1.y + qv.z * k1.z + qv.w * k1.w;
        d0 += __shfl_xor_sync(0xffffffffu, d0, 1);
        d1 += __shfl_xor_sync(0xffffffffu, d1, 1);
        d0 += __shfl_xor_sync(0xffffffffu, d0, 2);
        d1 += __shfl_xor_sync(0xffffffffu, d1, 2);
        float a0 = __expf(d0 * ph0);
        float a1 = __expf(d1 * ph1);
        den += a0 + a1;
        acc.x += a0 * m0.x + a1 * m1.x;
        acc.y += a0 * m0.y + a1 * m1.y;
        acc.z += a0 * m0.z + a1 * m1.z;
        acc.w += a0 * m0.w + a1 * m1.w;
    }
    if (i < end) {
        int pay = d_epay[i];
        unsigned u = (unsigned)pay;
        int src = pay & 0x7FFFFFFF;
        const __half* kb = (u >> 31) ? d_ktam : d_ktdm;
        const __half* mb = (u >> 31) ? d_mtam : d_mtdm;
        float ph = (u >> 31) ? p1 : p0;
        size_t b = (size_t)src * 128 + lane * 4;
        float4 k0, m0;
        half8_dot_acc(kb, b, k0);
        half8_dot_acc(mb, b, m0);
        float d0 = qv.x * k0.x + qv.y * k0.y + qv.z * k0.z + qv.w * k0.w;
        d0 += __shfl_xor_sync(0xffffffffu, d0, 1);
        d0 += __shfl_xor_sync(0xffffffffu, d0, 2);
        float a0 = __expf(d0 * ph);
        den += a0;
        acc.x += a0 * m0.x; acc.y += a0 * m0.y;
        acc.z += a0 * m0.z; acc.w += a0 * m0.w;
    }

    float inv = (den > 0.f) ? (1.f / den) : 0.f;
    float gl[4];
    gl[0] = gelu_exact(acc.x * inv);
    gl[1] = gelu_exact(acc.y * inv);
    gl[2] = gelu_exact(acc.z * inv);
    gl[3] = gelu_exact(acc.w * inv);

    float o[8] = {0, 0, 0, 0, 0, 0, 0, 0};
    int r0 = lane * 4;
#pragma unroll
    for (int j = 0; j < 4; j++) {
        float gj = gl[j];
        const float* wr = &sWc[(r0 + j) * 8];
#pragma unroll
        for (int c = 0; c < 8; c++) o[c] += gj * wr[c];
    }
#pragma unroll
    for (int off = 16; off > 0; off >>= 1)
#pragma unroll
        for (int c = 0; c < 8; c++) o[c] += __shfl_xor_sync(0xffffffffu, o[c], off);

    if (lane == 0) {
        float g = sc[0];
        const float* s0p = &d_s0[(size_t)node * 8];
        float4 o1, o2;
        o1.x = g * o[0] + (1.f - g) * s0p[0] + sc[1];
        o1.y = g * o[1] + (1.f - g) * s0p[1] + sc[2];
        o1.z = g * o[2] + (1.f - g) * s0p[2] + sc[3];
        o1.w = g * o[3] + (1.f - g) * s0p[3] + sc[4];
        o2.x = g * o[4] + (1.f - g) * s0p[4] + sc[5];
        o2.y = g * o[5] + (1.f - g) * s0p[5] + sc[6];
        o2.z = g * o[6] + (1.f - g) * s0p[6] + sc[7];
        o2.w = g * o[7] + (1.f - g) * s0p[7] + sc[8];
        *(float4*)&out[(size_t)node * 8] = o1;
        *(float4*)&out[(size_t)node * 8 + 4] = o2;
    }
}

// ---------------- launch ----------------
#define SYM(p, s) cudaGetSymbolAddress((void**)&(p), s)

extern "C" void kernel_launch(void* const* d_in, const int* in_sizes, int n_in,
                              void* d_out, int out_size) {
    (void)in_sizes; (void)n_in; (void)out_size;
    const float* x_m   = (const float*)d_in[0];
    const float* x_d   = (const float*)d_in[1];
    const float* x_a   = (const float*)d_in[2];
    const int* src_dm  = (const int*)d_in[3];
    const int* dst_dm  = (const int*)d_in[4];
    const int* src_am  = (const int*)d_in[5];
    const int* dst_am  = (const int*)d_in[6];
    const float* Wpre_m = (const float*)d_in[11];
    const float* Wpre_d = (const float*)d_in[12];
    const float* Wpre_a = (const float*)d_in[13];
    const float* bpre   = (const float*)d_in[14];
    const float* Wk     = (const float*)d_in[15];
    const float* bk     = (const float*)d_in[16];
    const float* Wq     = (const float*)d_in[17];
    const float* bq     = (const float*)d_in[18];
    const float* Wv     = (const float*)d_in[19];
    const float* bv     = (const float*)d_in[20];
    const float* a_rel  = (const float*)d_in[21];
    const float* m_rel  = (const float*)d_in[22];
    const float* p_rel  = (const float*)d_in[23];
    const float* skip   = (const float*)d_in[24];
    const float* Wa     = (const float*)d_in[25];
    const float* ba     = (const float*)d_in[26];
    const float* Wlin   = (const float*)d_in[27];
    const float* blin   = (const float*)d_in[28];
    float* out = (float*)d_out;

    int* counts;
    SYM(counts, d_counts);

    const int SMEM_G = (9216 + 8704 + 2048) * 4;   // 79872 B
    static int attr_set = 0;
    if (!attr_set) {
        cudaFuncSetAttribute(gemm_all, cudaFuncAttributeMaxDynamicSharedMemorySize, SMEM_G);
        attr_set = 1;
    }

    // 1) weight prep + counts clear
    cudaMemsetAsync(counts, 0, NM * sizeof(int));
    prep_compose<<<516, 128>>>(Wk, bk, Wv, bv, a_rel, m_rel);
    prep_mm<<<403, 256>>>(Wpre_m, Wpre_d, Wpre_a, bpre, Wq, bq, Wa, ba, Wlin);

    // 2) CSR by destination movie node
    count_edges<<<2344, 256>>>(dst_dm, dst_am);
    scan_block<<<NB, 1024>>>();
    scan_bsum<<<1, 32>>>();
    add_offsets<<<391, 256>>>();
    fill_edges<<<2344, 256>>>(dst_dm, dst_am, src_dm, src_am);

    // 3) all node-level GEMMs in one launch (tf32 MMA, cp.async pipeline; K/V emit fp16)
    gemm_all<<<1878, 256, SMEM_G>>>(x_m, x_d, x_a);

    // 4) fused attention + softmax aggregation + gelu + output head
    agg_out<<<12500, 256>>>(p_rel, skip, blin, out);
}